// round 13
// baseline (speedup 1.0000x reference)
#include <cuda_runtime.h>
#include <stdint.h>
#include <math.h>

// Problem constants
#define CB   32
#define CN   2048
#define CD   512
#define CNS  8
#define MROWS 65536          // CB*CN
#define SROWS 256            // CB*CNS
#define EPS_A 1e-8f
#define LN_EPS 1e-5f
#define ATT_SCALE 0.044194173824159216f  // 512^-0.5
#define NCHUNK 32            // token chunks (64 tokens each)

// ---------------- scratch (device globals; no allocation allowed) ----------
__device__ float g_xln[33554432];    // [65536][512] LN(inputs), fp32 (written by it0)
__device__ float g_kwT[262144];      // kw transposed
__device__ float g_vwT[262144];      // vw transposed
__device__ float g_wcat[1048576];    // [2048][512]: rows 0-511 v_w, rows 512-2047 w_ih@v_w
__device__ float g_bcat[2048];       // [v_b ; w_ih@v_b + b_ih]
__device__ float g_slots[131072];    // [256][512]
__device__ float g_q[131072];        // LN(slots)
__device__ float g_qk[131072];       // q contracted with kw
__device__ float g_qkb[256];         // q . k_b
__device__ float g_paw[4194304];     // [32 chunk][256][512] partial sm-weighted x
__device__ float g_pssum[8192];      // [32 chunk][256] partial softmax sums
__device__ float g_pxsum[524288];    // [32 chunk][32][512] partial x sums
__device__ float g_aw[131072];       // attention-weighted x (normalized)
__device__ float g_cat[524288];      // [256][2048]: cols 0-511 updates, 512-2047 gi
__device__ float g_gh[393216];       // [256][1536]
__device__ float g_s0[131072];
__device__ float g_h1[262144];
__device__ float g_h2[262144];
__device__ float g_h3[131072];

// ---------------- small helpers -------------------------------------------
__device__ __forceinline__ uint32_t f2tf(float f) {
    uint32_t u; asm("cvt.rna.tf32.f32 %0, %1;" : "=r"(u) : "f"(f)); return u;
}
__device__ __forceinline__ float geluf(float x) {
    return 0.5f * x * (1.0f + erff(x * 0.7071067811865476f));
}
__device__ __forceinline__ float sigm(float x) { return 1.0f / (1.0f + __expf(-x)); }
__device__ __forceinline__ float warp_sum(float v) {
#pragma unroll
    for (int o = 16; o; o >>= 1) v += __shfl_xor_sync(0xffffffffu, v, o);
    return v;
}
__device__ __forceinline__ void mma_tf32(float c[4], const uint32_t a[4], const uint32_t b[2]) {
    asm volatile(
        "mma.sync.aligned.m16n8k8.row.col.f32.tf32.tf32.f32 "
        "{%0,%1,%2,%3}, {%4,%5,%6,%7}, {%8,%9}, {%0,%1,%2,%3};\n"
        : "+f"(c[0]), "+f"(c[1]), "+f"(c[2]), "+f"(c[3])
        : "r"(a[0]), "r"(a[1]), "r"(a[2]), "r"(a[3]), "r"(b[0]), "r"(b[1]));
}
__device__ __forceinline__ uint32_t smem_u32(const void* p) {
    uint32_t a;
    asm("{ .reg .u64 t; cvta.to.shared.u64 t, %1; cvt.u32.u64 %0, t; }" : "=r"(a) : "l"(p));
    return a;
}
__device__ __forceinline__ void cpa16(uint32_t dst, const void* src) {
    asm volatile("cp.async.cg.shared.global [%0], [%1], 16;" :: "r"(dst), "l"(src));
}
#define CPA_COMMIT() asm volatile("cp.async.commit_group;" ::: "memory")
#define CPA_WAIT1()  asm volatile("cp.async.wait_group 1;" ::: "memory")
#define CPA_WAIT0()  asm volatile("cp.async.wait_group 0;" ::: "memory")

// ---------------- fused small kernels ---------------------------------------
__global__ void slot_init_ln_kernel(const float* __restrict__ noise, const float* __restrict__ mu,
                                    const float* __restrict__ ls,
                                    const float* __restrict__ g, const float* __restrict__ b,
                                    const float* __restrict__ kb) {
    int row = (blockIdx.x * 256 + threadIdx.x) >> 5;
    int lane = threadIdx.x & 31;
    const float4* nr = (const float4*)(noise + (size_t)row * CD);
    const float4* mu4 = (const float4*)mu;
    const float4* ls4 = (const float4*)ls;
    float4 v[4];
    float s = 0.f, s2 = 0.f;
#pragma unroll
    for (int i = 0; i < 4; i++) {
        int c = lane + 32 * i;
        float4 n4 = nr[c], m4 = mu4[c], l4 = ls4[c];
        v[i].x = m4.x + expf(l4.x) * n4.x;
        v[i].y = m4.y + expf(l4.y) * n4.y;
        v[i].z = m4.z + expf(l4.z) * n4.z;
        v[i].w = m4.w + expf(l4.w) * n4.w;
        ((float4*)(g_slots + (size_t)row * CD))[c] = v[i];
        s  += v[i].x + v[i].y + v[i].z + v[i].w;
        s2 += v[i].x * v[i].x + v[i].y * v[i].y + v[i].z * v[i].z + v[i].w * v[i].w;
    }
    s = warp_sum(s); s2 = warp_sum(s2);
    float m = s * (1.0f / CD);
    float var = s2 * (1.0f / CD) - m * m;
    float r = rsqrtf(var + LN_EPS);
    const float4* g4p = (const float4*)g;
    const float4* b4p = (const float4*)b;
    const float4* k4p = (const float4*)kb;
    float4* o = (float4*)(g_q + (size_t)row * CD);
    float qdot = 0.f;
#pragma unroll
    for (int i = 0; i < 4; i++) {
        int c = lane + 32 * i;
        float4 g4 = g4p[c], b4 = b4p[c], k4 = k4p[c];
        float4 ov;
        ov.x = (v[i].x - m) * r * g4.x + b4.x;
        ov.y = (v[i].y - m) * r * g4.y + b4.y;
        ov.z = (v[i].z - m) * r * g4.z + b4.z;
        ov.w = (v[i].w - m) * r * g4.w + b4.w;
        o[c] = ov;
        qdot += ov.x * k4.x + ov.y * k4.y + ov.z * k4.z + ov.w * k4.w;
    }
    qdot = warp_sum(qdot);
    if (lane == 0) g_qkb[row] = qdot;
}

__global__ void gru_ln_kernel(const float* __restrict__ g, const float* __restrict__ b,
                              const float* __restrict__ kb, float* __restrict__ outq) {
    int row = (blockIdx.x * 256 + threadIdx.x) >> 5;
    int lane = threadIdx.x & 31;
    const float4* cr  = (const float4*)(g_cat + (size_t)row * 2048);
    const float4* ghr = (const float4*)(g_gh + (size_t)row * 1536);
    float4* hr = (float4*)(g_slots + (size_t)row * CD);
    float4 v[4];
    float s = 0.f, s2 = 0.f;
#pragma unroll
    for (int i = 0; i < 4; i++) {
        int c = lane + 32 * i;
        float4 u  = cr[c];
        float4 ir = cr[128 + c], iz = cr[256 + c], in_ = cr[384 + c];
        float4 h_r = ghr[c], h_z = ghr[128 + c], h_n = ghr[256 + c];
        float4 h = hr[c];
        float4 nv;
        {
            float rg = sigm(ir.x + h_r.x), z = sigm(iz.x + h_z.x);
            nv.x = u.x + (1.0f - z) * tanhf(in_.x + rg * h_n.x) + z * h.x;
        }
        {
            float rg = sigm(ir.y + h_r.y), z = sigm(iz.y + h_z.y);
            nv.y = u.y + (1.0f - z) * tanhf(in_.y + rg * h_n.y) + z * h.y;
        }
        {
            float rg = sigm(ir.z + h_r.z), z = sigm(iz.z + h_z.z);
            nv.z = u.z + (1.0f - z) * tanhf(in_.z + rg * h_n.z) + z * h.z;
        }
        {
            float rg = sigm(ir.w + h_r.w), z = sigm(iz.w + h_z.w);
            nv.w = u.w + (1.0f - z) * tanhf(in_.w + rg * h_n.w) + z * h.w;
        }
        hr[c] = nv;
        v[i] = nv;
        s  += nv.x + nv.y + nv.z + nv.w;
        s2 += nv.x * nv.x + nv.y * nv.y + nv.z * nv.z + nv.w * nv.w;
    }
    s = warp_sum(s); s2 = warp_sum(s2);
    float m = s * (1.0f / CD);
    float var = s2 * (1.0f / CD) - m * m;
    float r = rsqrtf(var + LN_EPS);
    const float4* g4p = (const float4*)g;
    const float4* b4p = (const float4*)b;
    const float4* k4p = (const float4*)kb;
    float4* o = (float4*)(outq + (size_t)row * CD);
    float qdot = 0.f;
#pragma unroll
    for (int i = 0; i < 4; i++) {
        int c = lane + 32 * i;
        float4 g4 = g4p[c], b4 = b4p[c];
        float4 ov;
        ov.x = (v[i].x - m) * r * g4.x + b4.x;
        ov.y = (v[i].y - m) * r * g4.y + b4.y;
        ov.z = (v[i].z - m) * r * g4.z + b4.z;
        ov.w = (v[i].w - m) * r * g4.w + b4.w;
        o[c] = ov;
        if (kb) {
            float4 k4 = k4p[c];
            qdot += ov.x * k4.x + ov.y * k4.y + ov.z * k4.z + ov.w * k4.w;
        }
    }
    if (kb) {
        qdot = warp_sum(qdot);
        if (lane == 0) g_qkb[row] = qdot;
    }
}

// ---------------- prologue kernels -----------------------------------------
__global__ void transpose512_kernel(const float* __restrict__ src, float* __restrict__ dst) {
    __shared__ float t[32][33];
    int bx = blockIdx.x * 32, by = blockIdx.y * 32;
    int tx = threadIdx.x, ty = threadIdx.y;     // 32 x 8
#pragma unroll
    for (int i = 0; i < 32; i += 8)
        t[ty + i][tx] = src[(size_t)(by + ty + i) * 512 + bx + tx];
    __syncthreads();
#pragma unroll
    for (int i = 0; i < 32; i += 8)
        dst[(size_t)(bx + ty + i) * 512 + by + tx] = t[tx][ty + i];
}

__global__ void copy_vw_kernel(const float* __restrict__ vw, const float* __restrict__ vb) {
    int idx = blockIdx.x * 256 + threadIdx.x;        // 262144
    g_wcat[idx] = vw[idx];
    if (idx < 512) g_bcat[idx] = vb[idx];
}

__global__ void bc_kernel(const float* __restrict__ w_ih, const float* __restrict__ v_b,
                          const float* __restrict__ b_ih) {
    int j = blockIdx.x * 8 + (threadIdx.x >> 5);     // 0..1535
    int lane = threadIdx.x & 31;
    const float4* wr = (const float4*)(w_ih + (size_t)j * 512);
    const float4* vb4 = (const float4*)v_b;
    float s = 0.f;
#pragma unroll
    for (int i = 0; i < 4; i++) {
        float4 a = wr[lane + 32 * i], c = vb4[lane + 32 * i];
        s += a.x * c.x + a.y * c.y + a.z * c.z + a.w * c.w;
    }
    s = warp_sum(s);
    if (lane == 0) g_bcat[512 + j] = s + b_ih[j];
}

// ---------------- pipelined tf32 GEMM (cp.async, 3 stages) -------------------
#define GP_STRIDE 36
#define GP_TILE   (128 * GP_STRIDE)
#define GP_TILE_B (GP_TILE * 4)
#define GP_SMEM   (3 * 2 * GP_TILE_B)   // 110592

template <int ACT>
__device__ __forceinline__ void gemm_core_pipe(
    const float* __restrict__ A, int lda,
    const float* __restrict__ W, int ldw,
    const float* __restrict__ bias,
    float* __restrict__ C, int ldc, int K, int m0, int n0,
    float* __restrict__ C2, int c2cols) {
    extern __shared__ float sm[];
    float* As = sm;
    float* Bs = sm + 3 * GP_TILE;
    const uint32_t sa = smem_u32(As);
    const uint32_t sb = smem_u32(Bs);

    const int tid = threadIdx.x;
    const int warp = tid >> 5;
    const int lane = tid & 31;
    const int gid = lane >> 2;
    const int tig = lane & 3;
    const int mbase = (warp >> 2) * 64;
    const int nbase = (warp & 3) * 32;

    const int cr = tid >> 3;           // 0..31
    const int cc4 = (tid & 7) * 4;

    float c[4][4][4];
#pragma unroll
    for (int mi = 0; mi < 4; mi++)
#pragma unroll
        for (int ni = 0; ni < 4; ni++)
#pragma unroll
            for (int r = 0; r < 4; r++) c[mi][ni][r] = 0.f;

    const int NT = K >> 5;

#define GP_ISSUE(KT, ST)                                                           \
    do {                                                                           \
        uint32_t a_s = sa + (ST) * GP_TILE_B;                                      \
        uint32_t b_s = sb + (ST) * GP_TILE_B;                                      \
        _Pragma("unroll")                                                          \
        for (int i = 0; i < 4; i++) {                                              \
            int r = cr + i * 32;                                                   \
            cpa16(a_s + (r * GP_STRIDE + cc4) * 4,                                 \
                  A + (size_t)(m0 + r) * lda + (KT) * 32 + cc4);                   \
            cpa16(b_s + (r * GP_STRIDE + cc4) * 4,                                 \
                  W + (size_t)(n0 + r) * ldw + (KT) * 32 + cc4);                   \
        }                                                                          \
        CPA_COMMIT();                                                              \
    } while (0)

    GP_ISSUE(0, 0);
    GP_ISSUE(1, 1);

#pragma unroll 1
    for (int kt = 0; kt < NT; kt++) {
        if (kt < NT - 1) CPA_WAIT1(); else CPA_WAIT0();
        __syncthreads();
        if (kt + 2 < NT) GP_ISSUE(kt + 2, (kt + 2) % 3);

        const float* At = As + (kt % 3) * GP_TILE;
        const float* Bt = Bs + (kt % 3) * GP_TILE;
#pragma unroll
        for (int ks = 0; ks < 4; ks++) {
            uint32_t a[4][4], bf[4][2];
            int kk = ks * 8 + tig;
#pragma unroll
            for (int mi = 0; mi < 4; mi++) {
                const float* ap = At + (mbase + mi * 16 + gid) * GP_STRIDE;
                a[mi][0] = f2tf(ap[kk]);
                a[mi][1] = f2tf(ap[8 * GP_STRIDE + kk]);
                a[mi][2] = f2tf(ap[kk + 4]);
                a[mi][3] = f2tf(ap[8 * GP_STRIDE + kk + 4]);
            }
#pragma unroll
            for (int ni = 0; ni < 4; ni++) {
                const float* bp = Bt + (nbase + ni * 8 + gid) * GP_STRIDE;
                bf[ni][0] = f2tf(bp[kk]);
                bf[ni][1] = f2tf(bp[kk + 4]);
            }
#pragma unroll
            for (int mi = 0; mi < 4; mi++)
#pragma unroll
                for (int ni = 0; ni < 4; ni++) mma_tf32(c[mi][ni], a[mi], bf[ni]);
        }
        __syncthreads();
    }
#undef GP_ISSUE

#pragma unroll
    for (int mi = 0; mi < 4; mi++) {
        int r0 = m0 + mbase + mi * 16 + gid;
#pragma unroll
        for (int ni = 0; ni < 4; ni++) {
            int col = n0 + nbase + ni * 8 + tig * 2;
            float bv0 = bias ? __ldg(bias + col) : 0.f;
            float bv1 = bias ? __ldg(bias + col + 1) : 0.f;
            float v00 = c[mi][ni][0] + bv0, v01 = c[mi][ni][1] + bv1;
            float v10 = c[mi][ni][2] + bv0, v11 = c[mi][ni][3] + bv1;
            if (ACT == 1) { v00 = geluf(v00); v01 = geluf(v01); v10 = geluf(v10); v11 = geluf(v11); }
            *(float2*)(C + (size_t)r0 * ldc + col)       = make_float2(v00, v01);
            *(float2*)(C + (size_t)(r0 + 8) * ldc + col) = make_float2(v10, v11);
            if (C2 && col < c2cols) {
                *(float2*)(C2 + (size_t)r0 * c2cols + col)       = make_float2(v00, v01);
                *(float2*)(C2 + (size_t)(r0 + 8) * c2cols + col) = make_float2(v10, v11);
            }
        }
    }
}

template <int ACT>
__global__ __launch_bounds__(256) void gemm_tf32(
    const float* __restrict__ A, int lda,
    const float* __restrict__ W, int ldw,
    const float* __restrict__ bias,
    float* __restrict__ C, int ldc, int K) {
    gemm_core_pipe<ACT>(A, lda, W, ldw, bias, C, ldc, K,
                        blockIdx.y * 128, blockIdx.x * 128, nullptr, 0);
}

// per-iteration merged GEMM: z=0 -> [updates|gi] = aw @ W_cat^T + b_cat,
//                            z=1 -> gh = slots @ w_hh^T + b_hh
__global__ __launch_bounds__(256) void iter_gemm_dual(
    const float* __restrict__ w_hh, const float* __restrict__ b_hh,
    float* __restrict__ out2) {
    if (blockIdx.z == 0) {
        gemm_core_pipe<0>(g_aw, 512, g_wcat, 512, g_bcat, g_cat, 2048, 512,
                          blockIdx.y * 128, blockIdx.x * 128, out2, 512);
    } else {
        if (blockIdx.x >= 12) return;
        gemm_core_pipe<0>(g_slots, 512, w_hh, 512, b_hh, g_gh, 1536, 512,
                          blockIdx.y * 128, blockIdx.x * 128, nullptr, 0);
    }
}

// ---------------- fused attention pass (128 thr, q in regs, scattered softmax)
// 64-token chunks (8 subtiles), grid (32, 32) = 1024 CTAs for wave balance.
#define FA_TILE   0                         // 2 x 8 x 512 floats
#define FA_SMS    8192                      // 8 tok x 8 slots
#define FA_WSS    (FA_SMS + 64)             // 4 warps x 8
#define FA_LNG    (FA_WSS + 32)             // 512
#define FA_LNB    (FA_LNG + 512)            // 512
#define FA_FLOATS (FA_LNB + 512)
#define FA_SMEM   (FA_FLOATS * 4)           // 37248 B

template <bool LN0>
__global__ void __launch_bounds__(128, 2) fused_attn_kernel(
    const float* __restrict__ xsrc,
    const float* __restrict__ lng, const float* __restrict__ lnb) {
    extern __shared__ float sm[];
    float* tile = sm + FA_TILE;
    float* sms  = sm + FA_SMS;
    float* wss  = sm + FA_WSS;
    float* lngs = sm + FA_LNG;
    float* lnbs = sm + FA_LNB;
    const uint32_t tile_u = smem_u32(tile);

    const int chunk = blockIdx.x;        // 0..31 (64 tokens each)
    const int b     = blockIdx.y;
    const int tid   = threadIdx.x;
    const int warp  = tid >> 5;
    const int lane  = tid & 31;
    const int s_l = (((lane >> 4) & 1) << 2) | (((lane >> 3) & 1) << 1) | ((lane >> 2) & 1);

    // q cache: each lane holds its 16-float slice of all 8 q rows (registers)
    float4 qreg[8][4];
    {
        const float4* qg = (const float4*)(g_qk + (size_t)b * 4096);
#pragma unroll
        for (int s = 0; s < 8; s++)
#pragma unroll
            for (int cc = 0; cc < 4; cc++)
                qreg[s][cc] = qg[s * 128 + cc * 32 + lane];
    }
    const float qkb_s = __ldg(g_qkb + b * 8 + s_l);
    if (LN0) {
        for (int f = tid; f < 128; f += 128) {
            ((float4*)lngs)[f] = ((const float4*)lng)[f];
            ((float4*)lnbs)[f] = ((const float4*)lnb)[f];
        }
    }
    __syncthreads();

    const size_t jbase = (size_t)(b * CN + chunk * 64) * CD;
#define FA_ISSUE(ST)                                                               \
    do {                                                                           \
        uint32_t dst = tile_u + ((ST) & 1) * (4096 * 4);                           \
        _Pragma("unroll")                                                          \
        for (int i = 0; i < 8; i++) {                                              \
            int idx = tid + i * 128;                                               \
            int r = idx >> 7, c4 = (idx & 127) * 4;                                \
            cpa16(dst + (r * 512 + c4) * 4, xsrc + jbase + (size_t)((ST) * 8 + r) * 512 + c4); \
        }                                                                          \
        CPA_COMMIT();                                                              \
    } while (0)

    FA_ISSUE(0);

    float4 acc[8], accx;
#pragma unroll
    for (int s = 0; s < 8; s++) acc[s] = make_float4(0.f, 0.f, 0.f, 0.f);
    accx = make_float4(0.f, 0.f, 0.f, 0.f);
    float sswv = 0.f;

#pragma unroll 1
    for (int st = 0; st < 8; st++) {
        __syncthreads();
        if (st + 1 < 8) { FA_ISSUE(st + 1); CPA_WAIT1(); }
        else            { CPA_WAIT0(); }
        __syncthreads();
        float* tc = tile + (st & 1) * 4096;

        // Phase A: warp handles tokens tok0, tok0+1
        {
            const int tok0 = warp * 2;
            float4* xr0 = (float4*)(tc + tok0 * 512);
            float4* xr1 = xr0 + 128;
            float4 X0[4], X1[4];
#pragma unroll
            for (int cc = 0; cc < 4; cc++) {
                X0[cc] = xr0[cc * 32 + lane];
                X1[cc] = xr1[cc * 32 + lane];
            }
            if (LN0) {
                float s0 = 0.f, ss0 = 0.f, s1 = 0.f, ss1 = 0.f;
#pragma unroll
                for (int cc = 0; cc < 4; cc++) {
                    s0  += X0[cc].x + X0[cc].y + X0[cc].z + X0[cc].w;
                    ss0 += X0[cc].x * X0[cc].x + X0[cc].y * X0[cc].y + X0[cc].z * X0[cc].z + X0[cc].w * X0[cc].w;
                    s1  += X1[cc].x + X1[cc].y + X1[cc].z + X1[cc].w;
                    ss1 += X1[cc].x * X1[cc].x + X1[cc].y * X1[cc].y + X1[cc].z * X1[cc].z + X1[cc].w * X1[cc].w;
                }
                s0 = warp_sum(s0); ss0 = warp_sum(ss0);
                s1 = warp_sum(s1); ss1 = warp_sum(ss1);
                float m0 = s0 * (1.0f / CD);
                float r0 = rsqrtf(ss0 * (1.0f / CD) - m0 * m0 + LN_EPS);
                float m1 = s1 * (1.0f / CD);
                float r1 = rsqrtf(ss1 * (1.0f / CD) - m1 * m1 + LN_EPS);
                float4* gx0 = (float4*)(g_xln + jbase + (size_t)(st * 8 + tok0) * 512);
                float4* gx1 = gx0 + 128;
#pragma unroll
                for (int cc = 0; cc < 4; cc++) {
                    float4 g4 = ((const float4*)lngs)[cc * 32 + lane];
                    float4 b4 = ((const float4*)lnbs)[cc * 32 + lane];
                    float4 n0, n1;
                    n0.x = (X0[cc].x - m0) * r0 * g4.x + b4.x;
                    n0.y = (X0[cc].y - m0) * r0 * g4.y + b4.y;
                    n0.z = (X0[cc].z - m0) * r0 * g4.z + b4.z;
                    n0.w = (X0[cc].w - m0) * r0 * g4.w + b4.w;
                    n1.x = (X1[cc].x - m1) * r1 * g4.x + b4.x;
                    n1.y = (X1[cc].y - m1) * r1 * g4.y + b4.y;
                    n1.z = (X1[cc].z - m1) * r1 * g4.z + b4.z;
                    n1.w = (X1[cc].w - m1) * r1 * g4.w + b4.w;
                    X0[cc] = n0; X1[cc] = n1;
                    xr0[cc * 32 + lane] = n0;
                    xr1[cc * 32 + lane] = n1;
                    gx0[cc * 32 + lane] = n0;
                    gx1[cc * 32 + lane] = n1;
                }
            }
            float a0[8], a1[8];
#pragma unroll
            for (int s = 0; s < 8; s++) { a0[s] = 0.f; a1[s] = 0.f; }
#pragma unroll
            for (int cc = 0; cc < 4; cc++) {
#pragma unroll
                for (int s = 0; s < 8; s++) {
                    float4 q4 = qreg[s][cc];
                    a0[s] += X0[cc].x * q4.x + X0[cc].y * q4.y + X0[cc].z * q4.z + X0[cc].w * q4.w;
                    a1[s] += X1[cc].x * q4.x + X1[cc].y * q4.y + X1[cc].z * q4.z + X1[cc].w * q4.w;
                }
            }
            // tree reduction: scatter 8 slot-dots across lanes (bits 4,3,2)
#pragma unroll
            for (int j = 0; j < 4; j++) {
                float sd0 = (lane & 16) ? a0[j] : a0[j + 4];
                float sd1 = (lane & 16) ? a1[j] : a1[j + 4];
                float rv0 = __shfl_xor_sync(0xffffffffu, sd0, 16);
                float rv1 = __shfl_xor_sync(0xffffffffu, sd1, 16);
                a0[j] = ((lane & 16) ? a0[j + 4] : a0[j]) + rv0;
                a1[j] = ((lane & 16) ? a1[j + 4] : a1[j]) + rv1;
            }
#pragma unroll
            for (int j = 0; j < 2; j++) {
                float sd0 = (lane & 8) ? a0[j] : a0[j + 2];
                float sd1 = (lane & 8) ? a1[j] : a1[j + 2];
                float rv0 = __shfl_xor_sync(0xffffffffu, sd0, 8);
                float rv1 = __shfl_xor_sync(0xffffffffu, sd1, 8);
                a0[j] = ((lane & 8) ? a0[j + 2] : a0[j]) + rv0;
                a1[j] = ((lane & 8) ? a1[j + 2] : a1[j]) + rv1;
            }
            {
                float sd0 = (lane & 4) ? a0[0] : a0[1];
                float sd1 = (lane & 4) ? a1[0] : a1[1];
                float rv0 = __shfl_xor_sync(0xffffffffu, sd0, 4);
                float rv1 = __shfl_xor_sync(0xffffffffu, sd1, 4);
                a0[0] = ((lane & 4) ? a0[1] : a0[0]) + rv0;
                a1[0] = ((lane & 4) ? a1[1] : a1[0]) + rv1;
            }
            a0[0] += __shfl_xor_sync(0xffffffffu, a0[0], 2);
            a1[0] += __shfl_xor_sync(0xffffffffu, a1[0], 2);
            a0[0] += __shfl_xor_sync(0xffffffffu, a0[0], 1);
            a1[0] += __shfl_xor_sync(0xffffffffu, a1[0], 1);

            float v0 = a0[0] + qkb_s;
            float v1 = a1[0] + qkb_s;
            float mx0 = v0, mx1 = v1;
            mx0 = fmaxf(mx0, __shfl_xor_sync(0xffffffffu, mx0, 4));
            mx1 = fmaxf(mx1, __shfl_xor_sync(0xffffffffu, mx1, 4));
            mx0 = fmaxf(mx0, __shfl_xor_sync(0xffffffffu, mx0, 8));
            mx1 = fmaxf(mx1, __shfl_xor_sync(0xffffffffu, mx1, 8));
            mx0 = fmaxf(mx0, __shfl_xor_sync(0xffffffffu, mx0, 16));
            mx1 = fmaxf(mx1, __shfl_xor_sync(0xffffffffu, mx1, 16));
            float e0 = __expf((v0 - mx0) * ATT_SCALE);
            float e1 = __expf((v1 - mx1) * ATT_SCALE);
            float su0 = e0, su1 = e1;
            su0 += __shfl_xor_sync(0xffffffffu, su0, 4);
            su1 += __shfl_xor_sync(0xffffffffu, su1, 4);
            su0 += __shfl_xor_sync(0xffffffffu, su0, 8);
            su1 += __shfl_xor_sync(0xffffffffu, su1, 8);
            su0 += __shfl_xor_sync(0xffffffffu, su0, 16);
            su1 += __shfl_xor_sync(0xffffffffu, su1, 16);
            float sm0 = e0 / su0;
            float sm1 = e1 / su1;
            sswv += sm0 + sm1;
            if ((lane & 3) == 0) {
                sms[tok0 * 8 + s_l]       = sm0;
                sms[(tok0 + 1) * 8 + s_l] = sm1;
            }
        }
        __syncthreads();

        // Phase B: thread owns one float4 column
#pragma unroll
        for (int j = 0; j < 8; j++) {
            float4 s0 = ((const float4*)sms)[j * 2];
            float4 s1 = ((const float4*)sms)[j * 2 + 1];
            float4 x4 = ((const float4*)(tc + j * 512))[tid];
            acc[0].x += s0.x * x4.x; acc[0].y += s0.x * x4.y; acc[0].z += s0.x * x4.z; acc[0].w += s0.x * x4.w;
            acc[1].x += s0.y * x4.x; acc[1].y += s0.y * x4.y; acc[1].z += s0.y * x4.z; acc[1].w += s0.y * x4.w;
            acc[2].x += s0.z * x4.x; acc[2].y += s0.z * x4.y; acc[2].z += s0.z * x4.z; acc[2].w += s0.z * x4.w;
            acc[3].x += s0.w * x4.x; acc[3].y += s0.w * x4.y; acc[3].z += s0.w * x4.z; acc[3].w += s0.w * x4.w;
            acc[4].x += s1.x * x4.x; acc[4].y += s1.x * x4.y; acc[4].z += s1.x * x4.z; acc[4].w += s1.x * x4.w;
            acc[5].x += s1.y * x4.x; acc[5].y += s1.y * x4.y; acc[5].z += s1.y * x4.z; acc[5].w += s1.y * x4.w;
            acc[6].x += s1.z * x4.x; acc[6].y += s1.z * x4.y; acc[6].z += s1.z * x4.z; acc[6].w += s1.z * x4.w;
            acc[7].x += s1.w * x4.x; acc[7].y += s1.w * x4.y; acc[7].z += s1.w * x4.z; acc[7].w += s1.w * x4.w;
            accx.x += x4.x; accx.y += x4.y; accx.z += x4.z; accx.w += x4.w;
        }
    }
#undef FA_ISSUE

    // write partials (float4 stores, coalesced)
#pragma unroll
    for (int s = 0; s < 8; s++) {
        size_t row = (size_t)(chunk * 256 + b * 8 + s) * 512;
        ((float4*)(g_paw + row))[tid] = acc[s];
    }
    ((float4*)(g_pxsum + (size_t)(chunk * 32 + b) * 512))[tid] = accx;
    if ((lane & 3) == 0) wss[warp * 8 + s_l] = sswv;
    __syncthreads();
    if (tid < 8) {
        float t = 0.f;
#pragma unroll
        for (int w = 0; w < 4; w++) t += wss[w * 8 + tid];
        g_pssum[chunk * 256 + b * 8 + tid] = t;
    }
}

__global__ void aw_compose_kernel() {
    int idx = blockIdx.x * 256 + threadIdx.x;
    int row = idx >> 9;
    int d = idx & 511;
    int b = row >> 3;
    float den = 0.f, tot = 0.f, xs = 0.f;
#pragma unroll
    for (int c = 0; c < NCHUNK; c++) {
        den += g_pssum[c * 256 + row];
        tot += g_paw[(size_t)c * 131072 + (size_t)row * 512 + d];
        xs  += g_pxsum[(size_t)c * 16384 + (size_t)b * 512 + d];
    }
    float inv = 1.0f / (den + (float)CN * EPS_A);
    g_aw[idx] = (tot + EPS_A * xs) * inv;
}

// ---------------- launcher --------------------------------------------------
#define SYM(p, s) do { void* _v = nullptr; cudaGetSymbolAddress(&_v, s); (p) = (float*)_v; } while (0)

extern "C" void kernel_launch(void* const* d_in, const int* in_sizes, int n_in,
                              void* d_out, int out_size) {
    (void)in_sizes; (void)n_in; (void)out_size;
    const float* inputs         = (const float*)d_in[0];
    const float* slot_noise     = (const float*)d_in[1];
    const float* slots_mu       = (const float*)d_in[2];
    const float* slots_logsigma = (const float*)d_in[3];
    const float* k_w  = (const float*)d_in[4];
    const float* k_b  = (const float*)d_in[5];
    const float* v_w  = (const float*)d_in[6];
    const float* v_b  = (const float*)d_in[7];
    const float* gru_w_ih = (const float*)d_in[8];
    const float* gru_w_hh = (const float*)d_in[9];
    const float* gru_b_ih = (const float*)d_in[10];
    const float* gru_b_hh = (const float*)d_in[11];
    const float* ln_in_g = (const float*)d_in[12];
    const float* ln_in_b = (const float*)d_in[13];
    const float* ln_slots_g = (const float*)d_in[14];
    const float* ln_slots_b = (const float*)d_in[15];
    const float* ln_pre_g = (const float*)d_in[16];
    const float* ln_pre_b = (const float*)d_in[17];
    const float* mlp1_w = (const float*)d_in[18];
    const float* mlp1_b = (const float*)d_in[19];
    const float* mlp2_w = (const float*)d_in[20];
    const float* mlp2_b = (const float*)d_in[21];
    const float* mlp3_w = (const float*)d_in[22];
    const float* mlp3_b = (const float*)d_in[23];
    const float* mlp4_w = (const float*)d_in[24];
    const float* mlp4_b = (const float*)d_in[25];
    float* out = (float*)d_out;

    float *p_q, *p_qk, *p_kwT, *p_vwT, *p_wcat, *p_xln;
    float *p_s0, *p_h1, *p_h2, *p_h3;
    SYM(p_q, g_q); SYM(p_qk, g_qk);
    SYM(p_kwT, g_kwT); SYM(p_vwT, g_vwT); SYM(p_wcat, g_wcat); SYM(p_xln, g_xln);
    SYM(p_s0, g_s0); SYM(p_h1, g_h1); SYM(p_h2, g_h2); SYM(p_h3, g_h3);

    cudaFuncSetAttribute(fused_attn_kernel<true>,  cudaFuncAttributeMaxDynamicSharedMemorySize, FA_SMEM);
    cudaFuncSetAttribute(fused_attn_kernel<false>, cudaFuncAttributeMaxDynamicSharedMemorySize, FA_SMEM);
    cudaFuncSetAttribute(gemm_tf32<0>, cudaFuncAttributeMaxDynamicSharedMemorySize, GP_SMEM);
    cudaFuncSetAttribute(gemm_tf32<1>, cudaFuncAttributeMaxDynamicSharedMemorySize, GP_SMEM);
    cudaFuncSetAttribute(iter_gemm_dual, cudaFuncAttributeMaxDynamicSharedMemorySize, GP_SMEM);

    // critical path first (fused_attn is the 4th launch -> ncu samples it)
    transpose512_kernel<<<dim3(16, 16), dim3(32, 8)>>>(k_w, p_kwT);                    // 0
    slot_init_ln_kernel<<<32, 256>>>(slot_noise, slots_mu, slots_logsigma,
                                     ln_slots_g, ln_slots_b, k_b);                     // 1
    gemm_tf32<0><<<dim3(4, 2), 256, GP_SMEM>>>(p_q, 512, p_kwT, 512, nullptr,
                                               p_qk, 512, 512);                        // 2
    fused_attn_kernel<true><<<dim3(NCHUNK, 32), 128, FA_SMEM>>>(inputs, ln_in_g, ln_in_b); // 3
    aw_compose_kernel<<<512, 256>>>();                                                 // 4

    // prologue pieces needed only by iter_gemm
    transpose512_kernel<<<dim3(16, 16), dim3(32, 8)>>>(v_w, p_vwT);
    copy_vw_kernel<<<1024, 256>>>(v_w, v_b);
    gemm_tf32<0><<<dim3(4, 12), 256, GP_SMEM>>>(gru_w_ih, 512, p_vwT, 512, nullptr,
                                                p_wcat + 262144, 512, 512);
    bc_kernel<<<192, 256>>>(gru_w_ih, v_b, gru_b_ih);

    for (int it = 0; it < 3; it++) {
        if (it > 0) {
            gru_ln_kernel<<<32, 256>>>(ln_slots_g, ln_slots_b, k_b, p_q);
            gemm_tf32<0><<<dim3(4, 2), 256, GP_SMEM>>>(p_q, 512, p_kwT, 512, nullptr,
                                                       p_qk, 512, 512);
            fused_attn_kernel<false><<<dim3(NCHUNK, 32), 128, FA_SMEM>>>(p_xln, nullptr, nullptr);
            aw_compose_kernel<<<512, 256>>>();
        }
        iter_gemm_dual<<<dim3(16, 2, 2), 256, GP_SMEM>>>(gru_w_hh, gru_b_hh,
                                                         (it == 2) ? out : nullptr);
        if (it == 2) {
            gru_ln_kernel<<<32, 256>>>(ln_pre_g, ln_pre_b, nullptr, p_s0);
        }
    }

    gemm_tf32<1><<<dim3(8, 2), 256, GP_SMEM>>>(p_s0, 512, mlp1_w, 512, mlp1_b, p_h1, 1024, 512);
    gemm_tf32<1><<<dim3(8, 2), 256, GP_SMEM>>>(p_h1, 1024, mlp2_w, 1024, mlp2_b, p_h2, 1024, 1024);
    gemm_tf32<1><<<dim3(4, 2), 256, GP_SMEM>>>(p_h2, 1024, mlp3_w, 1024, mlp3_b, p_h3, 512, 1024);
    gemm_tf32<0><<<dim3(2, 2), 256, GP_SMEM>>>(p_h3, 512, mlp4_w, 512, mlp4_b, out + 131072, 256, 512);
}

// round 14
// speedup vs baseline: 1.0290x; 1.0290x over previous
#include <cuda_runtime.h>
#include <stdint.h>
#include <math.h>

// Problem constants
#define CB   32
#define CN   2048
#define CD   512
#define CNS  8
#define MROWS 65536          // CB*CN
#define SROWS 256            // CB*CNS
#define EPS_A 1e-8f
#define LN_EPS 1e-5f
#define ATT_SCALE 0.044194173824159216f  // 512^-0.5
#define NCHUNK 8             // token chunks (256 tokens each)

// ---------------- scratch (device globals; no allocation allowed) ----------
__device__ float g_xln[33554432];    // [65536][512] LN(inputs), fp32 (written by it0)
__device__ float g_kwT[262144];      // kw transposed
__device__ float g_vwT[262144];      // vw transposed
__device__ float g_wcat[1048576];    // [2048][512]: rows 0-511 v_w, rows 512-2047 w_ih@v_w
__device__ float g_bcat[2048];       // [v_b ; w_ih@v_b + b_ih]
__device__ float g_slots[131072];    // [256][512]
__device__ float g_q[131072];        // LN(slots)
__device__ float g_qk[131072];       // q contracted with kw
__device__ float g_qkb[256];         // q . k_b
__device__ float g_paw[1048576];     // [8 chunk][256][512] partial sm-weighted x
__device__ float g_pssum[2048];      // [8 chunk][256] partial softmax sums
__device__ float g_pxsum[131072];    // [8 chunk][32][512] partial x sums
__device__ float g_aw[131072];       // attention-weighted x (normalized)
__device__ float g_cat[524288];      // [256][2048]: cols 0-511 updates, 512-2047 gi
__device__ float g_gh[393216];       // [256][1536]
__device__ float g_s0[131072];
__device__ float g_h1[262144];
__device__ float g_h2[262144];
__device__ float g_h3[131072];

// ---------------- small helpers -------------------------------------------
__device__ __forceinline__ uint32_t f2tf(float f) {
    uint32_t u; asm("cvt.rna.tf32.f32 %0, %1;" : "=r"(u) : "f"(f)); return u;
}
__device__ __forceinline__ float geluf(float x) {
    return 0.5f * x * (1.0f + erff(x * 0.7071067811865476f));
}
__device__ __forceinline__ float sigm(float x) { return 1.0f / (1.0f + __expf(-x)); }
__device__ __forceinline__ float warp_sum(float v) {
#pragma unroll
    for (int o = 16; o; o >>= 1) v += __shfl_xor_sync(0xffffffffu, v, o);
    return v;
}
__device__ __forceinline__ void mma_tf32(float c[4], const uint32_t a[4], const uint32_t b[2]) {
    asm volatile(
        "mma.sync.aligned.m16n8k8.row.col.f32.tf32.tf32.f32 "
        "{%0,%1,%2,%3}, {%4,%5,%6,%7}, {%8,%9}, {%0,%1,%2,%3};\n"
        : "+f"(c[0]), "+f"(c[1]), "+f"(c[2]), "+f"(c[3])
        : "r"(a[0]), "r"(a[1]), "r"(a[2]), "r"(a[3]), "r"(b[0]), "r"(b[1]));
}
__device__ __forceinline__ uint32_t smem_u32(const void* p) {
    uint32_t a;
    asm("{ .reg .u64 t; cvta.to.shared.u64 t, %1; cvt.u32.u64 %0, t; }" : "=r"(a) : "l"(p));
    return a;
}
__device__ __forceinline__ void cpa16(uint32_t dst, const void* src) {
    asm volatile("cp.async.cg.shared.global [%0], [%1], 16;" :: "r"(dst), "l"(src));
}
#define CPA_COMMIT() asm volatile("cp.async.commit_group;" ::: "memory")
#define CPA_WAIT2()  asm volatile("cp.async.wait_group 2;" ::: "memory")
#define CPA_WAIT1()  asm volatile("cp.async.wait_group 1;" ::: "memory")
#define CPA_WAIT0()  asm volatile("cp.async.wait_group 0;" ::: "memory")

// ---------------- fused small kernels ---------------------------------------
__global__ void slot_init_ln_kernel(const float* __restrict__ noise, const float* __restrict__ mu,
                                    const float* __restrict__ ls,
                                    const float* __restrict__ g, const float* __restrict__ b,
                                    const float* __restrict__ kb) {
    int row = (blockIdx.x * 256 + threadIdx.x) >> 5;
    int lane = threadIdx.x & 31;
    const float4* nr = (const float4*)(noise + (size_t)row * CD);
    const float4* mu4 = (const float4*)mu;
    const float4* ls4 = (const float4*)ls;
    float4 v[4];
    float s = 0.f, s2 = 0.f;
#pragma unroll
    for (int i = 0; i < 4; i++) {
        int c = lane + 32 * i;
        float4 n4 = nr[c], m4 = mu4[c], l4 = ls4[c];
        v[i].x = m4.x + expf(l4.x) * n4.x;
        v[i].y = m4.y + expf(l4.y) * n4.y;
        v[i].z = m4.z + expf(l4.z) * n4.z;
        v[i].w = m4.w + expf(l4.w) * n4.w;
        ((float4*)(g_slots + (size_t)row * CD))[c] = v[i];
        s  += v[i].x + v[i].y + v[i].z + v[i].w;
        s2 += v[i].x * v[i].x + v[i].y * v[i].y + v[i].z * v[i].z + v[i].w * v[i].w;
    }
    s = warp_sum(s); s2 = warp_sum(s2);
    float m = s * (1.0f / CD);
    float var = s2 * (1.0f / CD) - m * m;
    float r = rsqrtf(var + LN_EPS);
    const float4* g4p = (const float4*)g;
    const float4* b4p = (const float4*)b;
    const float4* k4p = (const float4*)kb;
    float4* o = (float4*)(g_q + (size_t)row * CD);
    float qdot = 0.f;
#pragma unroll
    for (int i = 0; i < 4; i++) {
        int c = lane + 32 * i;
        float4 g4 = g4p[c], b4 = b4p[c], k4 = k4p[c];
        float4 ov;
        ov.x = (v[i].x - m) * r * g4.x + b4.x;
        ov.y = (v[i].y - m) * r * g4.y + b4.y;
        ov.z = (v[i].z - m) * r * g4.z + b4.z;
        ov.w = (v[i].w - m) * r * g4.w + b4.w;
        o[c] = ov;
        qdot += ov.x * k4.x + ov.y * k4.y + ov.z * k4.z + ov.w * k4.w;
    }
    qdot = warp_sum(qdot);
    if (lane == 0) g_qkb[row] = qdot;
}

__global__ void gru_ln_kernel(const float* __restrict__ g, const float* __restrict__ b,
                              const float* __restrict__ kb, float* __restrict__ outq) {
    int row = (blockIdx.x * 256 + threadIdx.x) >> 5;
    int lane = threadIdx.x & 31;
    const float4* cr  = (const float4*)(g_cat + (size_t)row * 2048);
    const float4* ghr = (const float4*)(g_gh + (size_t)row * 1536);
    float4* hr = (float4*)(g_slots + (size_t)row * CD);
    float4 v[4];
    float s = 0.f, s2 = 0.f;
#pragma unroll
    for (int i = 0; i < 4; i++) {
        int c = lane + 32 * i;
        float4 u  = cr[c];
        float4 ir = cr[128 + c], iz = cr[256 + c], in_ = cr[384 + c];
        float4 h_r = ghr[c], h_z = ghr[128 + c], h_n = ghr[256 + c];
        float4 h = hr[c];
        float4 nv;
        {
            float rg = sigm(ir.x + h_r.x), z = sigm(iz.x + h_z.x);
            nv.x = u.x + (1.0f - z) * tanhf(in_.x + rg * h_n.x) + z * h.x;
        }
        {
            float rg = sigm(ir.y + h_r.y), z = sigm(iz.y + h_z.y);
            nv.y = u.y + (1.0f - z) * tanhf(in_.y + rg * h_n.y) + z * h.y;
        }
        {
            float rg = sigm(ir.z + h_r.z), z = sigm(iz.z + h_z.z);
            nv.z = u.z + (1.0f - z) * tanhf(in_.z + rg * h_n.z) + z * h.z;
        }
        {
            float rg = sigm(ir.w + h_r.w), z = sigm(iz.w + h_z.w);
            nv.w = u.w + (1.0f - z) * tanhf(in_.w + rg * h_n.w) + z * h.w;
        }
        hr[c] = nv;
        v[i] = nv;
        s  += nv.x + nv.y + nv.z + nv.w;
        s2 += nv.x * nv.x + nv.y * nv.y + nv.z * nv.z + nv.w * nv.w;
    }
    s = warp_sum(s); s2 = warp_sum(s2);
    float m = s * (1.0f / CD);
    float var = s2 * (1.0f / CD) - m * m;
    float r = rsqrtf(var + LN_EPS);
    const float4* g4p = (const float4*)g;
    const float4* b4p = (const float4*)b;
    const float4* k4p = (const float4*)kb;
    float4* o = (float4*)(outq + (size_t)row * CD);
    float qdot = 0.f;
#pragma unroll
    for (int i = 0; i < 4; i++) {
        int c = lane + 32 * i;
        float4 g4 = g4p[c], b4 = b4p[c];
        float4 ov;
        ov.x = (v[i].x - m) * r * g4.x + b4.x;
        ov.y = (v[i].y - m) * r * g4.y + b4.y;
        ov.z = (v[i].z - m) * r * g4.z + b4.z;
        ov.w = (v[i].w - m) * r * g4.w + b4.w;
        o[c] = ov;
        if (kb) {
            float4 k4 = k4p[c];
            qdot += ov.x * k4.x + ov.y * k4.y + ov.z * k4.z + ov.w * k4.w;
        }
    }
    if (kb) {
        qdot = warp_sum(qdot);
        if (lane == 0) g_qkb[row] = qdot;
    }
}

// ---------------- prologue kernels -----------------------------------------
__global__ void transpose512_kernel(const float* __restrict__ src, float* __restrict__ dst) {
    __shared__ float t[32][33];
    int bx = blockIdx.x * 32, by = blockIdx.y * 32;
    int tx = threadIdx.x, ty = threadIdx.y;     // 32 x 8
#pragma unroll
    for (int i = 0; i < 32; i += 8)
        t[ty + i][tx] = src[(size_t)(by + ty + i) * 512 + bx + tx];
    __syncthreads();
#pragma unroll
    for (int i = 0; i < 32; i += 8)
        dst[(size_t)(bx + ty + i) * 512 + by + tx] = t[tx][ty + i];
}

__global__ void copy_vw_kernel(const float* __restrict__ vw, const float* __restrict__ vb) {
    int idx = blockIdx.x * 256 + threadIdx.x;        // 262144
    g_wcat[idx] = vw[idx];
    if (idx < 512) g_bcat[idx] = vb[idx];
}

__global__ void bc_kernel(const float* __restrict__ w_ih, const float* __restrict__ v_b,
                          const float* __restrict__ b_ih) {
    int j = blockIdx.x * 8 + (threadIdx.x >> 5);     // 0..1535
    int lane = threadIdx.x & 31;
    const float4* wr = (const float4*)(w_ih + (size_t)j * 512);
    const float4* vb4 = (const float4*)v_b;
    float s = 0.f;
#pragma unroll
    for (int i = 0; i < 4; i++) {
        float4 a = wr[lane + 32 * i], c = vb4[lane + 32 * i];
        s += a.x * c.x + a.y * c.y + a.z * c.z + a.w * c.w;
    }
    s = warp_sum(s);
    if (lane == 0) g_bcat[512 + j] = s + b_ih[j];
}

// ---------------- pipelined tf32 GEMM (cp.async, 3 stages) -------------------
#define GP_STRIDE 36
#define GP_TILE   (128 * GP_STRIDE)
#define GP_TILE_B (GP_TILE * 4)
#define GP_SMEM   (3 * 2 * GP_TILE_B)   // 110592

template <int ACT>
__device__ __forceinline__ void gemm_core_pipe(
    const float* __restrict__ A, int lda,
    const float* __restrict__ W, int ldw,
    const float* __restrict__ bias,
    float* __restrict__ C, int ldc, int K, int m0, int n0,
    float* __restrict__ C2, int c2cols) {
    extern __shared__ float sm[];
    float* As = sm;
    float* Bs = sm + 3 * GP_TILE;
    const uint32_t sa = smem_u32(As);
    const uint32_t sb = smem_u32(Bs);

    const int tid = threadIdx.x;
    const int warp = tid >> 5;
    const int lane = tid & 31;
    const int gid = lane >> 2;
    const int tig = lane & 3;
    const int mbase = (warp >> 2) * 64;
    const int nbase = (warp & 3) * 32;

    const int cr = tid >> 3;           // 0..31
    const int cc4 = (tid & 7) * 4;

    float c[4][4][4];
#pragma unroll
    for (int mi = 0; mi < 4; mi++)
#pragma unroll
        for (int ni = 0; ni < 4; ni++)
#pragma unroll
            for (int r = 0; r < 4; r++) c[mi][ni][r] = 0.f;

    const int NT = K >> 5;

#define GP_ISSUE(KT, ST)                                                           \
    do {                                                                           \
        uint32_t a_s = sa + (ST) * GP_TILE_B;                                      \
        uint32_t b_s = sb + (ST) * GP_TILE_B;                                      \
        _Pragma("unroll")                                                          \
        for (int i = 0; i < 4; i++) {                                              \
            int r = cr + i * 32;                                                   \
            cpa16(a_s + (r * GP_STRIDE + cc4) * 4,                                 \
                  A + (size_t)(m0 + r) * lda + (KT) * 32 + cc4);                   \
            cpa16(b_s + (r * GP_STRIDE + cc4) * 4,                                 \
                  W + (size_t)(n0 + r) * ldw + (KT) * 32 + cc4);                   \
        }                                                                          \
        CPA_COMMIT();                                                              \
    } while (0)

    GP_ISSUE(0, 0);
    GP_ISSUE(1, 1);

#pragma unroll 1
    for (int kt = 0; kt < NT; kt++) {
        if (kt < NT - 1) CPA_WAIT1(); else CPA_WAIT0();
        __syncthreads();
        if (kt + 2 < NT) GP_ISSUE(kt + 2, (kt + 2) % 3);

        const float* At = As + (kt % 3) * GP_TILE;
        const float* Bt = Bs + (kt % 3) * GP_TILE;
#pragma unroll
        for (int ks = 0; ks < 4; ks++) {
            uint32_t a[4][4], bf[4][2];
            int kk = ks * 8 + tig;
#pragma unroll
            for (int mi = 0; mi < 4; mi++) {
                const float* ap = At + (mbase + mi * 16 + gid) * GP_STRIDE;
                a[mi][0] = f2tf(ap[kk]);
                a[mi][1] = f2tf(ap[8 * GP_STRIDE + kk]);
                a[mi][2] = f2tf(ap[kk + 4]);
                a[mi][3] = f2tf(ap[8 * GP_STRIDE + kk + 4]);
            }
#pragma unroll
            for (int ni = 0; ni < 4; ni++) {
                const float* bp = Bt + (nbase + ni * 8 + gid) * GP_STRIDE;
                bf[ni][0] = f2tf(bp[kk]);
                bf[ni][1] = f2tf(bp[kk + 4]);
            }
#pragma unroll
            for (int mi = 0; mi < 4; mi++)
#pragma unroll
                for (int ni = 0; ni < 4; ni++) mma_tf32(c[mi][ni], a[mi], bf[ni]);
        }
        __syncthreads();
    }
#undef GP_ISSUE

#pragma unroll
    for (int mi = 0; mi < 4; mi++) {
        int r0 = m0 + mbase + mi * 16 + gid;
#pragma unroll
        for (int ni = 0; ni < 4; ni++) {
            int col = n0 + nbase + ni * 8 + tig * 2;
            float bv0 = bias ? __ldg(bias + col) : 0.f;
            float bv1 = bias ? __ldg(bias + col + 1) : 0.f;
            float v00 = c[mi][ni][0] + bv0, v01 = c[mi][ni][1] + bv1;
            float v10 = c[mi][ni][2] + bv0, v11 = c[mi][ni][3] + bv1;
            if (ACT == 1) { v00 = geluf(v00); v01 = geluf(v01); v10 = geluf(v10); v11 = geluf(v11); }
            *(float2*)(C + (size_t)r0 * ldc + col)       = make_float2(v00, v01);
            *(float2*)(C + (size_t)(r0 + 8) * ldc + col) = make_float2(v10, v11);
            if (C2 && col < c2cols) {
                *(float2*)(C2 + (size_t)r0 * c2cols + col)       = make_float2(v00, v01);
                *(float2*)(C2 + (size_t)(r0 + 8) * c2cols + col) = make_float2(v10, v11);
            }
        }
    }
}

template <int ACT>
__global__ __launch_bounds__(256) void gemm_tf32(
    const float* __restrict__ A, int lda,
    const float* __restrict__ W, int ldw,
    const float* __restrict__ bias,
    float* __restrict__ C, int ldc, int K) {
    gemm_core_pipe<ACT>(A, lda, W, ldw, bias, C, ldc, K,
                        blockIdx.y * 128, blockIdx.x * 128, nullptr, 0);
}

// per-iteration merged GEMM: z=0 -> [updates|gi] = aw @ W_cat^T + b_cat,
//                            z=1 -> gh = slots @ w_hh^T + b_hh
__global__ __launch_bounds__(256) void iter_gemm_dual(
    const float* __restrict__ w_hh, const float* __restrict__ b_hh,
    float* __restrict__ out2) {
    if (blockIdx.z == 0) {
        gemm_core_pipe<0>(g_aw, 512, g_wcat, 512, g_bcat, g_cat, 2048, 512,
                          blockIdx.y * 128, blockIdx.x * 128, out2, 512);
    } else {
        if (blockIdx.x >= 12) return;
        gemm_core_pipe<0>(g_slots, 512, w_hh, 512, b_hh, g_gh, 1536, 512,
                          blockIdx.y * 128, blockIdx.x * 128, nullptr, 0);
    }
}

// ---------------- fused attention pass (128 thr, q in regs, scattered softmax)
// 256-token chunks, 8-token subtiles, 3-stage cp.async pipeline (2 in flight).
#define FA_TILE   0                         // 3 x 8 x 512 floats
#define FA_SMS    12288                     // 8 tok x 8 slots
#define FA_WSS    (FA_SMS + 64)             // 4 warps x 8
#define FA_LNG    (FA_WSS + 32)             // 512
#define FA_LNB    (FA_LNG + 512)            // 512
#define FA_FLOATS (FA_LNB + 512)
#define FA_SMEM   (FA_FLOATS * 4)           // 53632 B

template <bool LN0>
__global__ void __launch_bounds__(128, 2) fused_attn_kernel(
    const float* __restrict__ xsrc,
    const float* __restrict__ lng, const float* __restrict__ lnb) {
    extern __shared__ float sm[];
    float* tile = sm + FA_TILE;
    float* sms  = sm + FA_SMS;
    float* wss  = sm + FA_WSS;
    float* lngs = sm + FA_LNG;
    float* lnbs = sm + FA_LNB;
    const uint32_t tile_u = smem_u32(tile);

    const int chunk = blockIdx.x;        // 0..7 (256 tokens each)
    const int b     = blockIdx.y;
    const int tid   = threadIdx.x;
    const int warp  = tid >> 5;
    const int lane  = tid & 31;
    const int s_l = (((lane >> 4) & 1) << 2) | (((lane >> 3) & 1) << 1) | ((lane >> 2) & 1);

    // q cache: each lane holds its 16-float slice of all 8 q rows (registers)
    float4 qreg[8][4];
    {
        const float4* qg = (const float4*)(g_qk + (size_t)b * 4096);
#pragma unroll
        for (int s = 0; s < 8; s++)
#pragma unroll
            for (int cc = 0; cc < 4; cc++)
                qreg[s][cc] = qg[s * 128 + cc * 32 + lane];
    }
    const float qkb_s = __ldg(g_qkb + b * 8 + s_l);
    if (LN0) {
        for (int f = tid; f < 128; f += 128) {
            ((float4*)lngs)[f] = ((const float4*)lng)[f];
            ((float4*)lnbs)[f] = ((const float4*)lnb)[f];
        }
    }
    __syncthreads();

    const size_t jbase = (size_t)(b * CN + chunk * 256) * CD;
#define FA_ISSUE(ST)                                                               \
    do {                                                                           \
        uint32_t dst = tile_u + ((ST) % 3) * (4096 * 4);                           \
        _Pragma("unroll")                                                          \
        for (int i = 0; i < 8; i++) {                                              \
            int idx = tid + i * 128;                                               \
            int r = idx >> 7, c4 = (idx & 127) * 4;                                \
            cpa16(dst + (r * 512 + c4) * 4, xsrc + jbase + (size_t)((ST) * 8 + r) * 512 + c4); \
        }                                                                          \
        CPA_COMMIT();                                                              \
    } while (0)

    FA_ISSUE(0);
    FA_ISSUE(1);

    float4 acc[8], accx;
#pragma unroll
    for (int s = 0; s < 8; s++) acc[s] = make_float4(0.f, 0.f, 0.f, 0.f);
    accx = make_float4(0.f, 0.f, 0.f, 0.f);
    float sswv = 0.f;

#pragma unroll 1
    for (int st = 0; st < 32; st++) {
        __syncthreads();                        // prior Phase B done (buffer reuse safe)
        if (st + 2 < 32) { FA_ISSUE(st + 2); CPA_WAIT2(); }
        else if (st + 1 < 32) CPA_WAIT1();
        else CPA_WAIT0();
        __syncthreads();                        // tile(st) visible
        float* tc = tile + (st % 3) * 4096;

        // Phase A: warp handles tokens tok0, tok0+1
        {
            const int tok0 = warp * 2;
            float4* xr0 = (float4*)(tc + tok0 * 512);
            float4* xr1 = xr0 + 128;
            float4 X0[4], X1[4];
#pragma unroll
            for (int cc = 0; cc < 4; cc++) {
                X0[cc] = xr0[cc * 32 + lane];
                X1[cc] = xr1[cc * 32 + lane];
            }
            if (LN0) {
                float s0 = 0.f, ss0 = 0.f, s1 = 0.f, ss1 = 0.f;
#pragma unroll
                for (int cc = 0; cc < 4; cc++) {
                    s0  += X0[cc].x + X0[cc].y + X0[cc].z + X0[cc].w;
                    ss0 += X0[cc].x * X0[cc].x + X0[cc].y * X0[cc].y + X0[cc].z * X0[cc].z + X0[cc].w * X0[cc].w;
                    s1  += X1[cc].x + X1[cc].y + X1[cc].z + X1[cc].w;
                    ss1 += X1[cc].x * X1[cc].x + X1[cc].y * X1[cc].y + X1[cc].z * X1[cc].z + X1[cc].w * X1[cc].w;
                }
                s0 = warp_sum(s0); ss0 = warp_sum(ss0);
                s1 = warp_sum(s1); ss1 = warp_sum(ss1);
                float m0 = s0 * (1.0f / CD);
                float r0 = rsqrtf(ss0 * (1.0f / CD) - m0 * m0 + LN_EPS);
                float m1 = s1 * (1.0f / CD);
                float r1 = rsqrtf(ss1 * (1.0f / CD) - m1 * m1 + LN_EPS);
                float4* gx0 = (float4*)(g_xln + jbase + (size_t)(st * 8 + tok0) * 512);
                float4* gx1 = gx0 + 128;
#pragma unroll
                for (int cc = 0; cc < 4; cc++) {
                    float4 g4 = ((const float4*)lngs)[cc * 32 + lane];
                    float4 b4 = ((const float4*)lnbs)[cc * 32 + lane];
                    float4 n0, n1;
                    n0.x = (X0[cc].x - m0) * r0 * g4.x + b4.x;
                    n0.y = (X0[cc].y - m0) * r0 * g4.y + b4.y;
                    n0.z = (X0[cc].z - m0) * r0 * g4.z + b4.z;
                    n0.w = (X0[cc].w - m0) * r0 * g4.w + b4.w;
                    n1.x = (X1[cc].x - m1) * r1 * g4.x + b4.x;
                    n1.y = (X1[cc].y - m1) * r1 * g4.y + b4.y;
                    n1.z = (X1[cc].z - m1) * r1 * g4.z + b4.z;
                    n1.w = (X1[cc].w - m1) * r1 * g4.w + b4.w;
                    X0[cc] = n0; X1[cc] = n1;
                    xr0[cc * 32 + lane] = n0;
                    xr1[cc * 32 + lane] = n1;
                    gx0[cc * 32 + lane] = n0;
                    gx1[cc * 32 + lane] = n1;
                }
            }
            float a0[8], a1[8];
#pragma unroll
            for (int s = 0; s < 8; s++) { a0[s] = 0.f; a1[s] = 0.f; }
#pragma unroll
            for (int cc = 0; cc < 4; cc++) {
#pragma unroll
                for (int s = 0; s < 8; s++) {
                    float4 q4 = qreg[s][cc];
                    a0[s] += X0[cc].x * q4.x + X0[cc].y * q4.y + X0[cc].z * q4.z + X0[cc].w * q4.w;
                    a1[s] += X1[cc].x * q4.x + X1[cc].y * q4.y + X1[cc].z * q4.z + X1[cc].w * q4.w;
                }
            }
            // tree reduction: scatter 8 slot-dots across lanes (bits 4,3,2)
#pragma unroll
            for (int j = 0; j < 4; j++) {
                float sd0 = (lane & 16) ? a0[j] : a0[j + 4];
                float sd1 = (lane & 16) ? a1[j] : a1[j + 4];
                float rv0 = __shfl_xor_sync(0xffffffffu, sd0, 16);
                float rv1 = __shfl_xor_sync(0xffffffffu, sd1, 16);
                a0[j] = ((lane & 16) ? a0[j + 4] : a0[j]) + rv0;
                a1[j] = ((lane & 16) ? a1[j + 4] : a1[j]) + rv1;
            }
#pragma unroll
            for (int j = 0; j < 2; j++) {
                float sd0 = (lane & 8) ? a0[j] : a0[j + 2];
                float sd1 = (lane & 8) ? a1[j] : a1[j + 2];
                float rv0 = __shfl_xor_sync(0xffffffffu, sd0, 8);
                float rv1 = __shfl_xor_sync(0xffffffffu, sd1, 8);
                a0[j] = ((lane & 8) ? a0[j + 2] : a0[j]) + rv0;
                a1[j] = ((lane & 8) ? a1[j + 2] : a1[j]) + rv1;
            }
            {
                float sd0 = (lane & 4) ? a0[0] : a0[1];
                float sd1 = (lane & 4) ? a1[0] : a1[1];
                float rv0 = __shfl_xor_sync(0xffffffffu, sd0, 4);
                float rv1 = __shfl_xor_sync(0xffffffffu, sd1, 4);
                a0[0] = ((lane & 4) ? a0[1] : a0[0]) + rv0;
                a1[0] = ((lane & 4) ? a1[1] : a1[0]) + rv1;
            }
            a0[0] += __shfl_xor_sync(0xffffffffu, a0[0], 2);
            a1[0] += __shfl_xor_sync(0xffffffffu, a1[0], 2);
            a0[0] += __shfl_xor_sync(0xffffffffu, a0[0], 1);
            a1[0] += __shfl_xor_sync(0xffffffffu, a1[0], 1);

            float v0 = a0[0] + qkb_s;
            float v1 = a1[0] + qkb_s;
            float mx0 = v0, mx1 = v1;
            mx0 = fmaxf(mx0, __shfl_xor_sync(0xffffffffu, mx0, 4));
            mx1 = fmaxf(mx1, __shfl_xor_sync(0xffffffffu, mx1, 4));
            mx0 = fmaxf(mx0, __shfl_xor_sync(0xffffffffu, mx0, 8));
            mx1 = fmaxf(mx1, __shfl_xor_sync(0xffffffffu, mx1, 8));
            mx0 = fmaxf(mx0, __shfl_xor_sync(0xffffffffu, mx0, 16));
            mx1 = fmaxf(mx1, __shfl_xor_sync(0xffffffffu, mx1, 16));
            float e0 = __expf((v0 - mx0) * ATT_SCALE);
            float e1 = __expf((v1 - mx1) * ATT_SCALE);
            float su0 = e0, su1 = e1;
            su0 += __shfl_xor_sync(0xffffffffu, su0, 4);
            su1 += __shfl_xor_sync(0xffffffffu, su1, 4);
            su0 += __shfl_xor_sync(0xffffffffu, su0, 8);
            su1 += __shfl_xor_sync(0xffffffffu, su1, 8);
            su0 += __shfl_xor_sync(0xffffffffu, su0, 16);
            su1 += __shfl_xor_sync(0xffffffffu, su1, 16);
            float sm0 = e0 / su0;
            float sm1 = e1 / su1;
            sswv += sm0 + sm1;
            if ((lane & 3) == 0) {
                sms[tok0 * 8 + s_l]       = sm0;
                sms[(tok0 + 1) * 8 + s_l] = sm1;
            }
        }
        __syncthreads();

        // Phase B: thread owns one float4 column
#pragma unroll
        for (int j = 0; j < 8; j++) {
            float4 s0 = ((const float4*)sms)[j * 2];
            float4 s1 = ((const float4*)sms)[j * 2 + 1];
            float4 x4 = ((const float4*)(tc + j * 512))[tid];
            acc[0].x += s0.x * x4.x; acc[0].y += s0.x * x4.y; acc[0].z += s0.x * x4.z; acc[0].w += s0.x * x4.w;
            acc[1].x += s0.y * x4.x; acc[1].y += s0.y * x4.y; acc[1].z += s0.y * x4.z; acc[1].w += s0.y * x4.w;
            acc[2].x += s0.z * x4.x; acc[2].y += s0.z * x4.y; acc[2].z += s0.z * x4.z; acc[2].w += s0.z * x4.w;
            acc[3].x += s0.w * x4.x; acc[3].y += s0.w * x4.y; acc[3].z += s0.w * x4.z; acc[3].w += s0.w * x4.w;
            acc[4].x += s1.x * x4.x; acc[4].y += s1.x * x4.y; acc[4].z += s1.x * x4.z; acc[4].w += s1.x * x4.w;
            acc[5].x += s1.y * x4.x; acc[5].y += s1.y * x4.y; acc[5].z += s1.y * x4.z; acc[5].w += s1.y * x4.w;
            acc[6].x += s1.z * x4.x; acc[6].y += s1.z * x4.y; acc[6].z += s1.z * x4.z; acc[6].w += s1.z * x4.w;
            acc[7].x += s1.w * x4.x; acc[7].y += s1.w * x4.y; acc[7].z += s1.w * x4.z; acc[7].w += s1.w * x4.w;
            accx.x += x4.x; accx.y += x4.y; accx.z += x4.z; accx.w += x4.w;
        }
    }
#undef FA_ISSUE

    // write partials (float4 stores, coalesced)
#pragma unroll
    for (int s = 0; s < 8; s++) {
        size_t row = (size_t)(chunk * 256 + b * 8 + s) * 512;
        ((float4*)(g_paw + row))[tid] = acc[s];
    }
    ((float4*)(g_pxsum + (size_t)(chunk * 32 + b) * 512))[tid] = accx;
    if ((lane & 3) == 0) wss[warp * 8 + s_l] = sswv;
    __syncthreads();
    if (tid < 8) {
        float t = 0.f;
#pragma unroll
        for (int w = 0; w < 4; w++) t += wss[w * 8 + tid];
        g_pssum[chunk * 256 + b * 8 + tid] = t;
    }
}

__global__ void aw_compose_kernel() {
    int idx = blockIdx.x * 256 + threadIdx.x;
    int row = idx >> 9;
    int d = idx & 511;
    int b = row >> 3;
    float den = 0.f, tot = 0.f, xs = 0.f;
#pragma unroll
    for (int c = 0; c < NCHUNK; c++) {
        den += g_pssum[c * 256 + row];
        tot += g_paw[(size_t)c * 131072 + (size_t)row * 512 + d];
        xs  += g_pxsum[(size_t)c * 16384 + (size_t)b * 512 + d];
    }
    float inv = 1.0f / (den + (float)CN * EPS_A);
    g_aw[idx] = (tot + EPS_A * xs) * inv;
}

// ---------------- launcher --------------------------------------------------
#define SYM(p, s) do { void* _v = nullptr; cudaGetSymbolAddress(&_v, s); (p) = (float*)_v; } while (0)

extern "C" void kernel_launch(void* const* d_in, const int* in_sizes, int n_in,
                              void* d_out, int out_size) {
    (void)in_sizes; (void)n_in; (void)out_size;
    const float* inputs         = (const float*)d_in[0];
    const float* slot_noise     = (const float*)d_in[1];
    const float* slots_mu       = (const float*)d_in[2];
    const float* slots_logsigma = (const float*)d_in[3];
    const float* k_w  = (const float*)d_in[4];
    const float* k_b  = (const float*)d_in[5];
    const float* v_w  = (const float*)d_in[6];
    const float* v_b  = (const float*)d_in[7];
    const float* gru_w_ih = (const float*)d_in[8];
    const float* gru_w_hh = (const float*)d_in[9];
    const float* gru_b_ih = (const float*)d_in[10];
    const float* gru_b_hh = (const float*)d_in[11];
    const float* ln_in_g = (const float*)d_in[12];
    const float* ln_in_b = (const float*)d_in[13];
    const float* ln_slots_g = (const float*)d_in[14];
    const float* ln_slots_b = (const float*)d_in[15];
    const float* ln_pre_g = (const float*)d_in[16];
    const float* ln_pre_b = (const float*)d_in[17];
    const float* mlp1_w = (const float*)d_in[18];
    const float* mlp1_b = (const float*)d_in[19];
    const float* mlp2_w = (const float*)d_in[20];
    const float* mlp2_b = (const float*)d_in[21];
    const float* mlp3_w = (const float*)d_in[22];
    const float* mlp3_b = (const float*)d_in[23];
    const float* mlp4_w = (const float*)d_in[24];
    const float* mlp4_b = (const float*)d_in[25];
    float* out = (float*)d_out;

    float *p_q, *p_qk, *p_kwT, *p_vwT, *p_wcat, *p_xln;
    float *p_s0, *p_h1, *p_h2, *p_h3;
    SYM(p_q, g_q); SYM(p_qk, g_qk);
    SYM(p_kwT, g_kwT); SYM(p_vwT, g_vwT); SYM(p_wcat, g_wcat); SYM(p_xln, g_xln);
    SYM(p_s0, g_s0); SYM(p_h1, g_h1); SYM(p_h2, g_h2); SYM(p_h3, g_h3);

    cudaFuncSetAttribute(fused_attn_kernel<true>,  cudaFuncAttributeMaxDynamicSharedMemorySize, FA_SMEM);
    cudaFuncSetAttribute(fused_attn_kernel<false>, cudaFuncAttributeMaxDynamicSharedMemorySize, FA_SMEM);
    cudaFuncSetAttribute(gemm_tf32<0>, cudaFuncAttributeMaxDynamicSharedMemorySize, GP_SMEM);
    cudaFuncSetAttribute(gemm_tf32<1>, cudaFuncAttributeMaxDynamicSharedMemorySize, GP_SMEM);
    cudaFuncSetAttribute(iter_gemm_dual, cudaFuncAttributeMaxDynamicSharedMemorySize, GP_SMEM);

    // critical path first (fused_attn is the 4th launch -> ncu samples it)
    transpose512_kernel<<<dim3(16, 16), dim3(32, 8)>>>(k_w, p_kwT);                    // 0
    slot_init_ln_kernel<<<32, 256>>>(slot_noise, slots_mu, slots_logsigma,
                                     ln_slots_g, ln_slots_b, k_b);                     // 1
    gemm_tf32<0><<<dim3(4, 2), 256, GP_SMEM>>>(p_q, 512, p_kwT, 512, nullptr,
                                               p_qk, 512, 512);                        // 2
    fused_attn_kernel<true><<<dim3(NCHUNK, 32), 128, FA_SMEM>>>(inputs, ln_in_g, ln_in_b); // 3
    aw_compose_kernel<<<512, 256>>>();                                                 // 4

    // prologue pieces needed only by iter_gemm
    transpose512_kernel<<<dim3(16, 16), dim3(32, 8)>>>(v_w, p_vwT);
    copy_vw_kernel<<<1024, 256>>>(v_w, v_b);
    gemm_tf32<0><<<dim3(4, 12), 256, GP_SMEM>>>(gru_w_ih, 512, p_vwT, 512, nullptr,
                                                p_wcat + 262144, 512, 512);
    bc_kernel<<<192, 256>>>(gru_w_ih, v_b, gru_b_ih);

    for (int it = 0; it < 3; it++) {
        if (it > 0) {
            gru_ln_kernel<<<32, 256>>>(ln_slots_g, ln_slots_b, k_b, p_q);
            gemm_tf32<0><<<dim3(4, 2), 256, GP_SMEM>>>(p_q, 512, p_kwT, 512, nullptr,
                                                       p_qk, 512, 512);
            fused_attn_kernel<false><<<dim3(NCHUNK, 32), 128, FA_SMEM>>>(p_xln, nullptr, nullptr);
            aw_compose_kernel<<<512, 256>>>();
        }
        iter_gemm_dual<<<dim3(16, 2, 2), 256, GP_SMEM>>>(gru_w_hh, gru_b_hh,
                                                         (it == 2) ? out : nullptr);
        if (it == 2) {
            gru_ln_kernel<<<32, 256>>>(ln_pre_g, ln_pre_b, nullptr, p_s0);
        }
    }

    gemm_tf32<1><<<dim3(8, 2), 256, GP_SMEM>>>(p_s0, 512, mlp1_w, 512, mlp1_b, p_h1, 1024, 512);
    gemm_tf32<1><<<dim3(8, 2), 256, GP_SMEM>>>(p_h1, 1024, mlp2_w, 1024, mlp2_b, p_h2, 1024, 1024);
    gemm_tf32<1><<<dim3(4, 2), 256, GP_SMEM>>>(p_h2, 1024, mlp3_w, 1024, mlp3_b, p_h3, 512, 1024);
    gemm_tf32<0><<<dim3(2, 2), 256, GP_SMEM>>>(p_h3, 512, mlp4_w, 512, mlp4_b, out + 131072, 256, 512);
}

// round 15
// speedup vs baseline: 1.0388x; 1.0095x over previous
#include <cuda_runtime.h>
#include <stdint.h>
#include <math.h>

// Problem constants
#define CB   32
#define CN   2048
#define CD   512
#define CNS  8
#define MROWS 65536          // CB*CN
#define SROWS 256            // CB*CNS
#define EPS_A 1e-8f
#define LN_EPS 1e-5f
#define ATT_SCALE 0.044194173824159216f  // 512^-0.5
#define NCHUNK 8             // token chunks (256 tokens each)

// ---------------- scratch (device globals; no allocation allowed) ----------
__device__ float g_xln[33554432];    // [65536][512] LN(inputs), fp32 (written by it0)
__device__ float g_kwT[262144];      // kw transposed
__device__ float g_vwT[262144];      // vw transposed
__device__ float g_wcat[1048576];    // [2048][512]: rows 0-511 v_w, rows 512-2047 w_ih@v_w
__device__ float g_bcat[2048];       // [v_b ; w_ih@v_b + b_ih]
__device__ float g_slots[131072];    // [256][512]
__device__ float g_q[131072];        // LN(slots)
__device__ float g_qk[131072];       // q contracted with kw
__device__ float g_qkb[256];         // q . k_b
__device__ float g_paw[1048576];     // [8 chunk][256][512] partial sm-weighted x
__device__ float g_pssum[2048];      // [8 chunk][256] partial softmax sums
__device__ float g_pxsum[131072];    // [8 chunk][32][512] partial x sums
__device__ float g_aw[131072];       // attention-weighted x (normalized)
__device__ float g_cat[524288];      // [256][2048]: cols 0-511 updates, 512-2047 gi
__device__ float g_gh[393216];       // [256][1536]
__device__ float g_s0[131072];
__device__ float g_h1[262144];
__device__ float g_h2[262144];
__device__ float g_h3[131072];

// ---------------- small helpers -------------------------------------------
__device__ __forceinline__ uint32_t f2tf(float f) {
    uint32_t u; asm("cvt.rna.tf32.f32 %0, %1;" : "=r"(u) : "f"(f)); return u;
}
__device__ __forceinline__ float geluf(float x) {
    return 0.5f * x * (1.0f + erff(x * 0.7071067811865476f));
}
__device__ __forceinline__ float sigm(float x) { return 1.0f / (1.0f + __expf(-x)); }
__device__ __forceinline__ float warp_sum(float v) {
#pragma unroll
    for (int o = 16; o; o >>= 1) v += __shfl_xor_sync(0xffffffffu, v, o);
    return v;
}
__device__ __forceinline__ void mma_tf32(float c[4], const uint32_t a[4], const uint32_t b[2]) {
    asm volatile(
        "mma.sync.aligned.m16n8k8.row.col.f32.tf32.tf32.f32 "
        "{%0,%1,%2,%3}, {%4,%5,%6,%7}, {%8,%9}, {%0,%1,%2,%3};\n"
        : "+f"(c[0]), "+f"(c[1]), "+f"(c[2]), "+f"(c[3])
        : "r"(a[0]), "r"(a[1]), "r"(a[2]), "r"(a[3]), "r"(b[0]), "r"(b[1]));
}
__device__ __forceinline__ uint32_t smem_u32(const void* p) {
    uint32_t a;
    asm("{ .reg .u64 t; cvta.to.shared.u64 t, %1; cvt.u32.u64 %0, t; }" : "=r"(a) : "l"(p));
    return a;
}
__device__ __forceinline__ void cpa16(uint32_t dst, const void* src) {
    asm volatile("cp.async.cg.shared.global [%0], [%1], 16;" :: "r"(dst), "l"(src));
}
#define CPA_COMMIT() asm volatile("cp.async.commit_group;" ::: "memory")
#define CPA_WAIT1()  asm volatile("cp.async.wait_group 1;" ::: "memory")
#define CPA_WAIT0()  asm volatile("cp.async.wait_group 0;" ::: "memory")

// ---------------- fused small kernels ---------------------------------------
__global__ void slot_init_ln_kernel(const float* __restrict__ noise, const float* __restrict__ mu,
                                    const float* __restrict__ ls,
                                    const float* __restrict__ g, const float* __restrict__ b,
                                    const float* __restrict__ kb) {
    int row = (blockIdx.x * 256 + threadIdx.x) >> 5;
    int lane = threadIdx.x & 31;
    const float4* nr = (const float4*)(noise + (size_t)row * CD);
    const float4* mu4 = (const float4*)mu;
    const float4* ls4 = (const float4*)ls;
    float4 v[4];
    float s = 0.f, s2 = 0.f;
#pragma unroll
    for (int i = 0; i < 4; i++) {
        int c = lane + 32 * i;
        float4 n4 = nr[c], m4 = mu4[c], l4 = ls4[c];
        v[i].x = m4.x + expf(l4.x) * n4.x;
        v[i].y = m4.y + expf(l4.y) * n4.y;
        v[i].z = m4.z + expf(l4.z) * n4.z;
        v[i].w = m4.w + expf(l4.w) * n4.w;
        ((float4*)(g_slots + (size_t)row * CD))[c] = v[i];
        s  += v[i].x + v[i].y + v[i].z + v[i].w;
        s2 += v[i].x * v[i].x + v[i].y * v[i].y + v[i].z * v[i].z + v[i].w * v[i].w;
    }
    s = warp_sum(s); s2 = warp_sum(s2);
    float m = s * (1.0f / CD);
    float var = s2 * (1.0f / CD) - m * m;
    float r = rsqrtf(var + LN_EPS);
    const float4* g4p = (const float4*)g;
    const float4* b4p = (const float4*)b;
    const float4* k4p = (const float4*)kb;
    float4* o = (float4*)(g_q + (size_t)row * CD);
    float qdot = 0.f;
#pragma unroll
    for (int i = 0; i < 4; i++) {
        int c = lane + 32 * i;
        float4 g4 = g4p[c], b4 = b4p[c], k4 = k4p[c];
        float4 ov;
        ov.x = (v[i].x - m) * r * g4.x + b4.x;
        ov.y = (v[i].y - m) * r * g4.y + b4.y;
        ov.z = (v[i].z - m) * r * g4.z + b4.z;
        ov.w = (v[i].w - m) * r * g4.w + b4.w;
        o[c] = ov;
        qdot += ov.x * k4.x + ov.y * k4.y + ov.z * k4.z + ov.w * k4.w;
    }
    qdot = warp_sum(qdot);
    if (lane == 0) g_qkb[row] = qdot;
}

__global__ void gru_ln_kernel(const float* __restrict__ g, const float* __restrict__ b,
                              const float* __restrict__ kb, float* __restrict__ outq) {
    int row = (blockIdx.x * 256 + threadIdx.x) >> 5;
    int lane = threadIdx.x & 31;
    const float4* cr  = (const float4*)(g_cat + (size_t)row * 2048);
    const float4* ghr = (const float4*)(g_gh + (size_t)row * 1536);
    float4* hr = (float4*)(g_slots + (size_t)row * CD);
    float4 v[4];
    float s = 0.f, s2 = 0.f;
#pragma unroll
    for (int i = 0; i < 4; i++) {
        int c = lane + 32 * i;
        float4 u  = cr[c];
        float4 ir = cr[128 + c], iz = cr[256 + c], in_ = cr[384 + c];
        float4 h_r = ghr[c], h_z = ghr[128 + c], h_n = ghr[256 + c];
        float4 h = hr[c];
        float4 nv;
        {
            float rg = sigm(ir.x + h_r.x), z = sigm(iz.x + h_z.x);
            nv.x = u.x + (1.0f - z) * tanhf(in_.x + rg * h_n.x) + z * h.x;
        }
        {
            float rg = sigm(ir.y + h_r.y), z = sigm(iz.y + h_z.y);
            nv.y = u.y + (1.0f - z) * tanhf(in_.y + rg * h_n.y) + z * h.y;
        }
        {
            float rg = sigm(ir.z + h_r.z), z = sigm(iz.z + h_z.z);
            nv.z = u.z + (1.0f - z) * tanhf(in_.z + rg * h_n.z) + z * h.z;
        }
        {
            float rg = sigm(ir.w + h_r.w), z = sigm(iz.w + h_z.w);
            nv.w = u.w + (1.0f - z) * tanhf(in_.w + rg * h_n.w) + z * h.w;
        }
        hr[c] = nv;
        v[i] = nv;
        s  += nv.x + nv.y + nv.z + nv.w;
        s2 += nv.x * nv.x + nv.y * nv.y + nv.z * nv.z + nv.w * nv.w;
    }
    s = warp_sum(s); s2 = warp_sum(s2);
    float m = s * (1.0f / CD);
    float var = s2 * (1.0f / CD) - m * m;
    float r = rsqrtf(var + LN_EPS);
    const float4* g4p = (const float4*)g;
    const float4* b4p = (const float4*)b;
    const float4* k4p = (const float4*)kb;
    float4* o = (float4*)(outq + (size_t)row * CD);
    float qdot = 0.f;
#pragma unroll
    for (int i = 0; i < 4; i++) {
        int c = lane + 32 * i;
        float4 g4 = g4p[c], b4 = b4p[c];
        float4 ov;
        ov.x = (v[i].x - m) * r * g4.x + b4.x;
        ov.y = (v[i].y - m) * r * g4.y + b4.y;
        ov.z = (v[i].z - m) * r * g4.z + b4.z;
        ov.w = (v[i].w - m) * r * g4.w + b4.w;
        o[c] = ov;
        if (kb) {
            float4 k4 = k4p[c];
            qdot += ov.x * k4.x + ov.y * k4.y + ov.z * k4.z + ov.w * k4.w;
        }
    }
    if (kb) {
        qdot = warp_sum(qdot);
        if (lane == 0) g_qkb[row] = qdot;
    }
}

// ---------------- prologue kernels -----------------------------------------
__global__ void transpose512_kernel(const float* __restrict__ src, float* __restrict__ dst) {
    __shared__ float t[32][33];
    int bx = blockIdx.x * 32, by = blockIdx.y * 32;
    int tx = threadIdx.x, ty = threadIdx.y;     // 32 x 8
#pragma unroll
    for (int i = 0; i < 32; i += 8)
        t[ty + i][tx] = src[(size_t)(by + ty + i) * 512 + bx + tx];
    __syncthreads();
#pragma unroll
    for (int i = 0; i < 32; i += 8)
        dst[(size_t)(bx + ty + i) * 512 + by + tx] = t[tx][ty + i];
}

__global__ void copy_vw_kernel(const float* __restrict__ vw, const float* __restrict__ vb) {
    int idx = blockIdx.x * 256 + threadIdx.x;        // 262144
    g_wcat[idx] = vw[idx];
    if (idx < 512) g_bcat[idx] = vb[idx];
}

__global__ void bc_kernel(const float* __restrict__ w_ih, const float* __restrict__ v_b,
                          const float* __restrict__ b_ih) {
    int j = blockIdx.x * 8 + (threadIdx.x >> 5);     // 0..1535
    int lane = threadIdx.x & 31;
    const float4* wr = (const float4*)(w_ih + (size_t)j * 512);
    const float4* vb4 = (const float4*)v_b;
    float s = 0.f;
#pragma unroll
    for (int i = 0; i < 4; i++) {
        float4 a = wr[lane + 32 * i], c = vb4[lane + 32 * i];
        s += a.x * c.x + a.y * c.y + a.z * c.z + a.w * c.w;
    }
    s = warp_sum(s);
    if (lane == 0) g_bcat[512 + j] = s + b_ih[j];
}

// ---------------- pipelined tf32 GEMM (cp.async, 3 stages) -------------------
#define GP_STRIDE 36
#define GP_TILE   (128 * GP_STRIDE)
#define GP_TILE_B (GP_TILE * 4)
#define GP_SMEM   (3 * 2 * GP_TILE_B)   // 110592

template <int ACT>
__device__ __forceinline__ void gemm_core_pipe(
    const float* __restrict__ A, int lda,
    const float* __restrict__ W, int ldw,
    const float* __restrict__ bias,
    float* __restrict__ C, int ldc, int K, int m0, int n0,
    float* __restrict__ C2, int c2cols) {
    extern __shared__ float sm[];
    float* As = sm;
    float* Bs = sm + 3 * GP_TILE;
    const uint32_t sa = smem_u32(As);
    const uint32_t sb = smem_u32(Bs);

    const int tid = threadIdx.x;
    const int warp = tid >> 5;
    const int lane = tid & 31;
    const int gid = lane >> 2;
    const int tig = lane & 3;
    const int mbase = (warp >> 2) * 64;
    const int nbase = (warp & 3) * 32;

    const int cr = tid >> 3;           // 0..31
    const int cc4 = (tid & 7) * 4;

    float c[4][4][4];
#pragma unroll
    for (int mi = 0; mi < 4; mi++)
#pragma unroll
        for (int ni = 0; ni < 4; ni++)
#pragma unroll
            for (int r = 0; r < 4; r++) c[mi][ni][r] = 0.f;

    const int NT = K >> 5;

#define GP_ISSUE(KT, ST)                                                           \
    do {                                                                           \
        uint32_t a_s = sa + (ST) * GP_TILE_B;                                      \
        uint32_t b_s = sb + (ST) * GP_TILE_B;                                      \
        _Pragma("unroll")                                                          \
        for (int i = 0; i < 4; i++) {                                              \
            int r = cr + i * 32;                                                   \
            cpa16(a_s + (r * GP_STRIDE + cc4) * 4,                                 \
                  A + (size_t)(m0 + r) * lda + (KT) * 32 + cc4);                   \
            cpa16(b_s + (r * GP_STRIDE + cc4) * 4,                                 \
                  W + (size_t)(n0 + r) * ldw + (KT) * 32 + cc4);                   \
        }                                                                          \
        CPA_COMMIT();                                                              \
    } while (0)

    GP_ISSUE(0, 0);
    GP_ISSUE(1, 1);

#pragma unroll 1
    for (int kt = 0; kt < NT; kt++) {
        if (kt < NT - 1) CPA_WAIT1(); else CPA_WAIT0();
        __syncthreads();
        if (kt + 2 < NT) GP_ISSUE(kt + 2, (kt + 2) % 3);

        const float* At = As + (kt % 3) * GP_TILE;
        const float* Bt = Bs + (kt % 3) * GP_TILE;
#pragma unroll
        for (int ks = 0; ks < 4; ks++) {
            uint32_t a[4][4], bf[4][2];
            int kk = ks * 8 + tig;
#pragma unroll
            for (int mi = 0; mi < 4; mi++) {
                const float* ap = At + (mbase + mi * 16 + gid) * GP_STRIDE;
                a[mi][0] = f2tf(ap[kk]);
                a[mi][1] = f2tf(ap[8 * GP_STRIDE + kk]);
                a[mi][2] = f2tf(ap[kk + 4]);
                a[mi][3] = f2tf(ap[8 * GP_STRIDE + kk + 4]);
            }
#pragma unroll
            for (int ni = 0; ni < 4; ni++) {
                const float* bp = Bt + (nbase + ni * 8 + gid) * GP_STRIDE;
                bf[ni][0] = f2tf(bp[kk]);
                bf[ni][1] = f2tf(bp[kk + 4]);
            }
#pragma unroll
            for (int mi = 0; mi < 4; mi++)
#pragma unroll
                for (int ni = 0; ni < 4; ni++) mma_tf32(c[mi][ni], a[mi], bf[ni]);
        }
        __syncthreads();
    }
#undef GP_ISSUE

#pragma unroll
    for (int mi = 0; mi < 4; mi++) {
        int r0 = m0 + mbase + mi * 16 + gid;
#pragma unroll
        for (int ni = 0; ni < 4; ni++) {
            int col = n0 + nbase + ni * 8 + tig * 2;
            float bv0 = bias ? __ldg(bias + col) : 0.f;
            float bv1 = bias ? __ldg(bias + col + 1) : 0.f;
            float v00 = c[mi][ni][0] + bv0, v01 = c[mi][ni][1] + bv1;
            float v10 = c[mi][ni][2] + bv0, v11 = c[mi][ni][3] + bv1;
            if (ACT == 1) { v00 = geluf(v00); v01 = geluf(v01); v10 = geluf(v10); v11 = geluf(v11); }
            *(float2*)(C + (size_t)r0 * ldc + col)       = make_float2(v00, v01);
            *(float2*)(C + (size_t)(r0 + 8) * ldc + col) = make_float2(v10, v11);
            if (C2 && col < c2cols) {
                *(float2*)(C2 + (size_t)r0 * c2cols + col)       = make_float2(v00, v01);
                *(float2*)(C2 + (size_t)(r0 + 8) * c2cols + col) = make_float2(v10, v11);
            }
        }
    }
}

template <int ACT>
__global__ __launch_bounds__(256) void gemm_tf32(
    const float* __restrict__ A, int lda,
    const float* __restrict__ W, int ldw,
    const float* __restrict__ bias,
    float* __restrict__ C, int ldc, int K) {
    gemm_core_pipe<ACT>(A, lda, W, ldw, bias, C, ldc, K,
                        blockIdx.y * 128, blockIdx.x * 128, nullptr, 0);
}

// gh = slots @ w_hh^T + b_hh   (grid 12x2; runs on side stream)
__global__ __launch_bounds__(256) void gh_gemm(
    const float* __restrict__ w_hh, const float* __restrict__ b_hh) {
    gemm_core_pipe<0>(g_slots, 512, w_hh, 512, b_hh, g_gh, 1536, 512,
                      blockIdx.y * 128, blockIdx.x * 128, nullptr, 0);
}

// [updates|gi] = aw @ W_cat^T + b_cat  (grid 16x2)
__global__ __launch_bounds__(256) void cat_gemm(float* __restrict__ out2) {
    gemm_core_pipe<0>(g_aw, 512, g_wcat, 512, g_bcat, g_cat, 2048, 512,
                      blockIdx.y * 128, blockIdx.x * 128, out2, 512);
}

// ---------------- fused attention pass (128 thr, q in regs, scattered softmax)
#define FA_TILE   0                         // 2 x 8 x 512 floats
#define FA_SMS    8192                      // 8 tok x 8 slots
#define FA_WSS    (FA_SMS + 64)             // 4 warps x 8
#define FA_LNG    (FA_WSS + 32)             // 512
#define FA_LNB    (FA_LNG + 512)            // 512
#define FA_FLOATS (FA_LNB + 512)
#define FA_SMEM   (FA_FLOATS * 4)           // 37248 B

template <bool LN0>
__global__ void __launch_bounds__(128, 2) fused_attn_kernel(
    const float* __restrict__ xsrc,
    const float* __restrict__ lng, const float* __restrict__ lnb) {
    extern __shared__ float sm[];
    float* tile = sm + FA_TILE;
    float* sms  = sm + FA_SMS;
    float* wss  = sm + FA_WSS;
    float* lngs = sm + FA_LNG;
    float* lnbs = sm + FA_LNB;
    const uint32_t tile_u = smem_u32(tile);

    const int chunk = blockIdx.x;        // 0..7 (256 tokens each)
    const int b     = blockIdx.y;
    const int tid   = threadIdx.x;
    const int warp  = tid >> 5;
    const int lane  = tid & 31;
    const int s_l = (((lane >> 4) & 1) << 2) | (((lane >> 3) & 1) << 1) | ((lane >> 2) & 1);

    // q cache: each lane holds its 16-float slice of all 8 q rows (registers)
    float4 qreg[8][4];
    {
        const float4* qg = (const float4*)(g_qk + (size_t)b * 4096);
#pragma unroll
        for (int s = 0; s < 8; s++)
#pragma unroll
            for (int cc = 0; cc < 4; cc++)
                qreg[s][cc] = qg[s * 128 + cc * 32 + lane];
    }
    const float qkb_s = __ldg(g_qkb + b * 8 + s_l);
    if (LN0) {
        for (int f = tid; f < 128; f += 128) {
            ((float4*)lngs)[f] = ((const float4*)lng)[f];
            ((float4*)lnbs)[f] = ((const float4*)lnb)[f];
        }
    }
    __syncthreads();

    const size_t jbase = (size_t)(b * CN + chunk * 256) * CD;
#define FA_ISSUE(ST)                                                               \
    do {                                                                           \
        uint32_t dst = tile_u + ((ST) & 1) * (4096 * 4);                           \
        _Pragma("unroll")                                                          \
        for (int i = 0; i < 8; i++) {                                              \
            int idx = tid + i * 128;                                               \
            int r = idx >> 7, c4 = (idx & 127) * 4;                                \
            cpa16(dst + (r * 512 + c4) * 4, xsrc + jbase + (size_t)((ST) * 8 + r) * 512 + c4); \
        }                                                                          \
        CPA_COMMIT();                                                              \
    } while (0)

    FA_ISSUE(0);

    float4 acc[8], accx;
#pragma unroll
    for (int s = 0; s < 8; s++) acc[s] = make_float4(0.f, 0.f, 0.f, 0.f);
    accx = make_float4(0.f, 0.f, 0.f, 0.f);
    float sswv = 0.f;

#pragma unroll 1
    for (int st = 0; st < 32; st++) {
        __syncthreads();
        if (st + 1 < 32) { FA_ISSUE(st + 1); CPA_WAIT1(); }
        else             { CPA_WAIT0(); }
        __syncthreads();
        float* tc = tile + (st & 1) * 4096;

        // Phase A: warp handles tokens tok0, tok0+1
        {
            const int tok0 = warp * 2;
            float4* xr0 = (float4*)(tc + tok0 * 512);
            float4* xr1 = xr0 + 128;
            float4 X0[4], X1[4];
#pragma unroll
            for (int cc = 0; cc < 4; cc++) {
                X0[cc] = xr0[cc * 32 + lane];
                X1[cc] = xr1[cc * 32 + lane];
            }
            if (LN0) {
                float s0 = 0.f, ss0 = 0.f, s1 = 0.f, ss1 = 0.f;
#pragma unroll
                for (int cc = 0; cc < 4; cc++) {
                    s0  += X0[cc].x + X0[cc].y + X0[cc].z + X0[cc].w;
                    ss0 += X0[cc].x * X0[cc].x + X0[cc].y * X0[cc].y + X0[cc].z * X0[cc].z + X0[cc].w * X0[cc].w;
                    s1  += X1[cc].x + X1[cc].y + X1[cc].z + X1[cc].w;
                    ss1 += X1[cc].x * X1[cc].x + X1[cc].y * X1[cc].y + X1[cc].z * X1[cc].z + X1[cc].w * X1[cc].w;
                }
                s0 = warp_sum(s0); ss0 = warp_sum(ss0);
                s1 = warp_sum(s1); ss1 = warp_sum(ss1);
                float m0 = s0 * (1.0f / CD);
                float r0 = rsqrtf(ss0 * (1.0f / CD) - m0 * m0 + LN_EPS);
                float m1 = s1 * (1.0f / CD);
                float r1 = rsqrtf(ss1 * (1.0f / CD) - m1 * m1 + LN_EPS);
                float4* gx0 = (float4*)(g_xln + jbase + (size_t)(st * 8 + tok0) * 512);
                float4* gx1 = gx0 + 128;
#pragma unroll
                for (int cc = 0; cc < 4; cc++) {
                    float4 g4 = ((const float4*)lngs)[cc * 32 + lane];
                    float4 b4 = ((const float4*)lnbs)[cc * 32 + lane];
                    float4 n0, n1;
                    n0.x = (X0[cc].x - m0) * r0 * g4.x + b4.x;
                    n0.y = (X0[cc].y - m0) * r0 * g4.y + b4.y;
                    n0.z = (X0[cc].z - m0) * r0 * g4.z + b4.z;
                    n0.w = (X0[cc].w - m0) * r0 * g4.w + b4.w;
                    n1.x = (X1[cc].x - m1) * r1 * g4.x + b4.x;
                    n1.y = (X1[cc].y - m1) * r1 * g4.y + b4.y;
                    n1.z = (X1[cc].z - m1) * r1 * g4.z + b4.z;
                    n1.w = (X1[cc].w - m1) * r1 * g4.w + b4.w;
                    X0[cc] = n0; X1[cc] = n1;
                    xr0[cc * 32 + lane] = n0;
                    xr1[cc * 32 + lane] = n1;
                    gx0[cc * 32 + lane] = n0;
                    gx1[cc * 32 + lane] = n1;
                }
            }
            float a0[8], a1[8];
#pragma unroll
            for (int s = 0; s < 8; s++) { a0[s] = 0.f; a1[s] = 0.f; }
#pragma unroll
            for (int cc = 0; cc < 4; cc++) {
#pragma unroll
                for (int s = 0; s < 8; s++) {
                    float4 q4 = qreg[s][cc];
                    a0[s] += X0[cc].x * q4.x + X0[cc].y * q4.y + X0[cc].z * q4.z + X0[cc].w * q4.w;
                    a1[s] += X1[cc].x * q4.x + X1[cc].y * q4.y + X1[cc].z * q4.z + X1[cc].w * q4.w;
                }
            }
            // tree reduction: scatter 8 slot-dots across lanes (bits 4,3,2)
#pragma unroll
            for (int j = 0; j < 4; j++) {
                float sd0 = (lane & 16) ? a0[j] : a0[j + 4];
                float sd1 = (lane & 16) ? a1[j] : a1[j + 4];
                float rv0 = __shfl_xor_sync(0xffffffffu, sd0, 16);
                float rv1 = __shfl_xor_sync(0xffffffffu, sd1, 16);
                a0[j] = ((lane & 16) ? a0[j + 4] : a0[j]) + rv0;
                a1[j] = ((lane & 16) ? a1[j + 4] : a1[j]) + rv1;
            }
#pragma unroll
            for (int j = 0; j < 2; j++) {
                float sd0 = (lane & 8) ? a0[j] : a0[j + 2];
                float sd1 = (lane & 8) ? a1[j] : a1[j + 2];
                float rv0 = __shfl_xor_sync(0xffffffffu, sd0, 8);
                float rv1 = __shfl_xor_sync(0xffffffffu, sd1, 8);
                a0[j] = ((lane & 8) ? a0[j + 2] : a0[j]) + rv0;
                a1[j] = ((lane & 8) ? a1[j + 2] : a1[j]) + rv1;
            }
            {
                float sd0 = (lane & 4) ? a0[0] : a0[1];
                float sd1 = (lane & 4) ? a1[0] : a1[1];
                float rv0 = __shfl_xor_sync(0xffffffffu, sd0, 4);
                float rv1 = __shfl_xor_sync(0xffffffffu, sd1, 4);
                a0[0] = ((lane & 4) ? a0[1] : a0[0]) + rv0;
                a1[0] = ((lane & 4) ? a1[1] : a1[0]) + rv1;
            }
            a0[0] += __shfl_xor_sync(0xffffffffu, a0[0], 2);
            a1[0] += __shfl_xor_sync(0xffffffffu, a1[0], 2);
            a0[0] += __shfl_xor_sync(0xffffffffu, a0[0], 1);
            a1[0] += __shfl_xor_sync(0xffffffffu, a1[0], 1);

            float v0 = a0[0] + qkb_s;
            float v1 = a1[0] + qkb_s;
            float mx0 = v0, mx1 = v1;
            mx0 = fmaxf(mx0, __shfl_xor_sync(0xffffffffu, mx0, 4));
            mx1 = fmaxf(mx1, __shfl_xor_sync(0xffffffffu, mx1, 4));
            mx0 = fmaxf(mx0, __shfl_xor_sync(0xffffffffu, mx0, 8));
            mx1 = fmaxf(mx1, __shfl_xor_sync(0xffffffffu, mx1, 8));
            mx0 = fmaxf(mx0, __shfl_xor_sync(0xffffffffu, mx0, 16));
            mx1 = fmaxf(mx1, __shfl_xor_sync(0xffffffffu, mx1, 16));
            float e0 = __expf((v0 - mx0) * ATT_SCALE);
            float e1 = __expf((v1 - mx1) * ATT_SCALE);
            float su0 = e0, su1 = e1;
            su0 += __shfl_xor_sync(0xffffffffu, su0, 4);
            su1 += __shfl_xor_sync(0xffffffffu, su1, 4);
            su0 += __shfl_xor_sync(0xffffffffu, su0, 8);
            su1 += __shfl_xor_sync(0xffffffffu, su1, 8);
            su0 += __shfl_xor_sync(0xffffffffu, su0, 16);
            su1 += __shfl_xor_sync(0xffffffffu, su1, 16);
            float sm0 = e0 / su0;
            float sm1 = e1 / su1;
            sswv += sm0 + sm1;
            if ((lane & 3) == 0) {
                sms[tok0 * 8 + s_l]       = sm0;
                sms[(tok0 + 1) * 8 + s_l] = sm1;
            }
        }
        __syncthreads();

        // Phase B: thread owns one float4 column
#pragma unroll
        for (int j = 0; j < 8; j++) {
            float4 s0 = ((const float4*)sms)[j * 2];
            float4 s1 = ((const float4*)sms)[j * 2 + 1];
            float4 x4 = ((const float4*)(tc + j * 512))[tid];
            acc[0].x += s0.x * x4.x; acc[0].y += s0.x * x4.y; acc[0].z += s0.x * x4.z; acc[0].w += s0.x * x4.w;
            acc[1].x += s0.y * x4.x; acc[1].y += s0.y * x4.y; acc[1].z += s0.y * x4.z; acc[1].w += s0.y * x4.w;
            acc[2].x += s0.z * x4.x; acc[2].y += s0.z * x4.y; acc[2].z += s0.z * x4.z; acc[2].w += s0.z * x4.w;
            acc[3].x += s0.w * x4.x; acc[3].y += s0.w * x4.y; acc[3].z += s0.w * x4.z; acc[3].w += s0.w * x4.w;
            acc[4].x += s1.x * x4.x; acc[4].y += s1.x * x4.y; acc[4].z += s1.x * x4.z; acc[4].w += s1.x * x4.w;
            acc[5].x += s1.y * x4.x; acc[5].y += s1.y * x4.y; acc[5].z += s1.y * x4.z; acc[5].w += s1.y * x4.w;
            acc[6].x += s1.z * x4.x; acc[6].y += s1.z * x4.y; acc[6].z += s1.z * x4.z; acc[6].w += s1.z * x4.w;
            acc[7].x += s1.w * x4.x; acc[7].y += s1.w * x4.y; acc[7].z += s1.w * x4.z; acc[7].w += s1.w * x4.w;
            accx.x += x4.x; accx.y += x4.y; accx.z += x4.z; accx.w += x4.w;
        }
    }
#undef FA_ISSUE

    // write partials (float4 stores, coalesced)
#pragma unroll
    for (int s = 0; s < 8; s++) {
        size_t row = (size_t)(chunk * 256 + b * 8 + s) * 512;
        ((float4*)(g_paw + row))[tid] = acc[s];
    }
    ((float4*)(g_pxsum + (size_t)(chunk * 32 + b) * 512))[tid] = accx;
    if ((lane & 3) == 0) wss[warp * 8 + s_l] = sswv;
    __syncthreads();
    if (tid < 8) {
        float t = 0.f;
#pragma unroll
        for (int w = 0; w < 4; w++) t += wss[w * 8 + tid];
        g_pssum[chunk * 256 + b * 8 + tid] = t;
    }
}

__global__ void aw_compose_kernel() {
    int idx = blockIdx.x * 256 + threadIdx.x;
    int row = idx >> 9;
    int d = idx & 511;
    int b = row >> 3;
    float den = 0.f, tot = 0.f, xs = 0.f;
#pragma unroll
    for (int c = 0; c < NCHUNK; c++) {
        den += g_pssum[c * 256 + row];
        tot += g_paw[(size_t)c * 131072 + (size_t)row * 512 + d];
        xs  += g_pxsum[(size_t)c * 16384 + (size_t)b * 512 + d];
    }
    float inv = 1.0f / (den + (float)CN * EPS_A);
    g_aw[idx] = (tot + EPS_A * xs) * inv;
}

// ---------------- launcher --------------------------------------------------
#define SYM(p, s) do { void* _v = nullptr; cudaGetSymbolAddress(&_v, s); (p) = (float*)_v; } while (0)

extern "C" void kernel_launch(void* const* d_in, const int* in_sizes, int n_in,
                              void* d_out, int out_size) {
    (void)in_sizes; (void)n_in; (void)out_size;
    const float* inputs         = (const float*)d_in[0];
    const float* slot_noise     = (const float*)d_in[1];
    const float* slots_mu       = (const float*)d_in[2];
    const float* slots_logsigma = (const float*)d_in[3];
    const float* k_w  = (const float*)d_in[4];
    const float* k_b  = (const float*)d_in[5];
    const float* v_w  = (const float*)d_in[6];
    const float* v_b  = (const float*)d_in[7];
    const float* gru_w_ih = (const float*)d_in[8];
    const float* gru_w_hh = (const float*)d_in[9];
    const float* gru_b_ih = (const float*)d_in[10];
    const float* gru_b_hh = (const float*)d_in[11];
    const float* ln_in_g = (const float*)d_in[12];
    const float* ln_in_b = (const float*)d_in[13];
    const float* ln_slots_g = (const float*)d_in[14];
    const float* ln_slots_b = (const float*)d_in[15];
    const float* ln_pre_g = (const float*)d_in[16];
    const float* ln_pre_b = (const float*)d_in[17];
    const float* mlp1_w = (const float*)d_in[18];
    const float* mlp1_b = (const float*)d_in[19];
    const float* mlp2_w = (const float*)d_in[20];
    const float* mlp2_b = (const float*)d_in[21];
    const float* mlp3_w = (const float*)d_in[22];
    const float* mlp3_b = (const float*)d_in[23];
    const float* mlp4_w = (const float*)d_in[24];
    const float* mlp4_b = (const float*)d_in[25];
    float* out = (float*)d_out;

    float *p_q, *p_qk, *p_kwT, *p_vwT, *p_wcat, *p_xln;
    float *p_s0, *p_h1, *p_h2, *p_h3;
    SYM(p_q, g_q); SYM(p_qk, g_qk);
    SYM(p_kwT, g_kwT); SYM(p_vwT, g_vwT); SYM(p_wcat, g_wcat); SYM(p_xln, g_xln);
    SYM(p_s0, g_s0); SYM(p_h1, g_h1); SYM(p_h2, g_h2); SYM(p_h3, g_h3);

    cudaFuncSetAttribute(fused_attn_kernel<true>,  cudaFuncAttributeMaxDynamicSharedMemorySize, FA_SMEM);
    cudaFuncSetAttribute(fused_attn_kernel<false>, cudaFuncAttributeMaxDynamicSharedMemorySize, FA_SMEM);
    cudaFuncSetAttribute(gemm_tf32<0>, cudaFuncAttributeMaxDynamicSharedMemorySize, GP_SMEM);
    cudaFuncSetAttribute(gemm_tf32<1>, cudaFuncAttributeMaxDynamicSharedMemorySize, GP_SMEM);
    cudaFuncSetAttribute(gh_gemm, cudaFuncAttributeMaxDynamicSharedMemorySize, GP_SMEM);
    cudaFuncSetAttribute(cat_gemm, cudaFuncAttributeMaxDynamicSharedMemorySize, GP_SMEM);

    // side stream + events (created per call; safe to leak — capture forbids
    // destroying a participating stream before EndCapture)
    cudaStream_t s2 = 0;
    cudaStreamCreateWithFlags(&s2, cudaStreamNonBlocking);
    cudaEvent_t evA = nullptr, evB = nullptr;
    cudaEventCreateWithFlags(&evA, cudaEventDisableTiming);
    cudaEventCreateWithFlags(&evB, cudaEventDisableTiming);

    // main chain start
    transpose512_kernel<<<dim3(16, 16), dim3(32, 8)>>>(k_w, p_kwT);
    slot_init_ln_kernel<<<32, 256>>>(slot_noise, slots_mu, slots_logsigma,
                                     ln_slots_g, ln_slots_b, k_b);

    // fork: side chain (prologue for W_cat + gh of iteration 0)
    cudaEventRecord(evA, 0);
    cudaStreamWaitEvent(s2, evA, 0);
    transpose512_kernel<<<dim3(16, 16), dim3(32, 8), 0, s2>>>(v_w, p_vwT);
    copy_vw_kernel<<<1024, 256, 0, s2>>>(v_w, v_b);
    gemm_tf32<0><<<dim3(4, 12), 256, GP_SMEM, s2>>>(gru_w_ih, 512, p_vwT, 512, nullptr,
                                                    p_wcat + 262144, 512, 512);
    bc_kernel<<<192, 256, 0, s2>>>(gru_w_ih, v_b, gru_b_ih);
    gh_gemm<<<dim3(12, 2), 256, GP_SMEM, s2>>>(gru_w_hh, gru_b_hh);
    cudaEventRecord(evB, s2);

    // main chain continues concurrently
    gemm_tf32<0><<<dim3(4, 2), 256, GP_SMEM>>>(p_q, 512, p_kwT, 512, nullptr,
                                               p_qk, 512, 512);
    fused_attn_kernel<true><<<dim3(NCHUNK, 32), 128, FA_SMEM>>>(inputs, ln_in_g, ln_in_b);
    aw_compose_kernel<<<512, 256>>>();
    cudaStreamWaitEvent(0, evB, 0);
    cat_gemm<<<dim3(16, 2), 256, GP_SMEM>>>(nullptr);

    for (int it = 1; it < 3; it++) {
        gru_ln_kernel<<<32, 256>>>(ln_slots_g, ln_slots_b, k_b, p_q);
        // fork gh onto side stream (depends only on slots)
        cudaEventRecord(evA, 0);
        cudaStreamWaitEvent(s2, evA, 0);
        gh_gemm<<<dim3(12, 2), 256, GP_SMEM, s2>>>(gru_w_hh, gru_b_hh);
        cudaEventRecord(evB, s2);
        // main chain
        gemm_tf32<0><<<dim3(4, 2), 256, GP_SMEM>>>(p_q, 512, p_kwT, 512, nullptr,
                                                   p_qk, 512, 512);
        fused_attn_kernel<false><<<dim3(NCHUNK, 32), 128, FA_SMEM>>>(p_xln, nullptr, nullptr);
        aw_compose_kernel<<<512, 256>>>();
        cudaStreamWaitEvent(0, evB, 0);
        cat_gemm<<<dim3(16, 2), 256, GP_SMEM>>>((it == 2) ? out : nullptr);
    }

    // final GRU + pre-MLP LayerNorm, then MLP head
    gru_ln_kernel<<<32, 256>>>(ln_pre_g, ln_pre_b, nullptr, p_s0);
    gemm_tf32<1><<<dim3(8, 2), 256, GP_SMEM>>>(p_s0, 512, mlp1_w, 512, mlp1_b, p_h1, 1024, 512);
    gemm_tf32<1><<<dim3(8, 2), 256, GP_SMEM>>>(p_h1, 1024, mlp2_w, 1024, mlp2_b, p_h2, 1024, 1024);
    gemm_tf32<1><<<dim3(4, 2), 256, GP_SMEM>>>(p_h2, 1024, mlp3_w, 1024, mlp3_b, p_h3, 512, 1024);
    gemm_tf32<0><<<dim3(2, 2), 256, GP_SMEM>>>(p_h3, 512, mlp4_w, 512, mlp4_b, out + 131072, 256, 512);
}